// round 1
// baseline (speedup 1.0000x reference)
#include <cuda_runtime.h>
#include <math.h>

#define NN 100000
#define FF 128
#define HH 64
#define CC 16
#define EE 1000000

// ---------------- scratch (device globals; no allocation allowed) ----------
__device__ __align__(16) float g_h0[NN * HH];
__device__ __align__(16) float g_x1[NN * HH];
__device__ __align__(16) float g_x2[NN * HH];
__device__ __align__(16) float g_xmid[NN * HH];

// ---------------- zero the two scatter buffers ------------------------------
__global__ void k_zero() {
    const int tot = NN * HH / 4;
    float4 z = make_float4(0.f, 0.f, 0.f, 0.f);
    for (int i = blockIdx.x * blockDim.x + threadIdx.x; i < tot;
         i += gridDim.x * blockDim.x) {
        reinterpret_cast<float4*>(g_x1)[i] = z;
        reinterpret_cast<float4*>(g_x2)[i] = z;
    }
}

// ---------------- first linear: h0 = x @ W_first^T + b ----------------------
// 8 nodes/block, 64 threads per node. W staged transposed (k-major) in smem.
__global__ __launch_bounds__(512) void k_first(const float* __restrict__ x,
                                               const float* __restrict__ W,
                                               const float* __restrict__ b) {
    __shared__ float Ws[FF * HH];   // Ws[f*64 + h] = W[h][f]
    __shared__ float xs[8 * FF];
    int t = threadIdx.x;
    for (int i = t; i < HH * FF; i += 512) {
        int h = i >> 7, f = i & 127;
        Ws[f * HH + h] = W[i];
    }
    int base = blockIdx.x * 8;
    for (int i = t; i < 8 * FF; i += 512) xs[i] = x[base * FF + i];
    __syncthreads();

    int c = t & 63, ln = t >> 6;
    float acc = b[c];
    const float* xr = &xs[ln * FF];
#pragma unroll 8
    for (int f = 0; f < FF; f++) acc += xr[f] * Ws[f * HH + c];
    g_h0[(base + ln) * HH + c] = acc;
}

// ---------------- edge propagation: one warp per edge -----------------------
// slot < E  : forward edges  -> g_x1
// slot >= E : reverse edges  -> g_x2
__global__ __launch_bounds__(256) void k_prop(int use_mid,
                                              const int* __restrict__ ei1,
                                              const float* __restrict__ ew1,
                                              const int* __restrict__ ei2,
                                              const float* __restrict__ ew2) {
    const float* xin = use_mid ? g_xmid : g_h0;
    int slot = blockIdx.x * 8 + (threadIdx.x >> 5);
    int lane = threadIdx.x & 31;

    const int* ei;
    const float* ew;
    float* out;
    int e;
    if (slot < EE) { e = slot;      ei = ei1; ew = ew1; out = g_x1; }
    else           { e = slot - EE; ei = ei2; ew = ew2; out = g_x2; }

    int src = __ldg(ei + e);
    int dst = __ldg(ei + EE + e);
    float w = __ldg(ew + e);

    float2 v = *reinterpret_cast<const float2*>(xin + src * HH + 2 * lane);
    float* o = out + dst * HH + 2 * lane;
    atomicAdd(o,     v.x * w);
    atomicAdd(o + 1, v.y * w);
}

// ---------------- fused concat-linear + GRU + (lin1 | out+log_softmax) ------
// 16 nodes/block, 64 threads/node = 1024 threads. All weights in dynamic smem,
// transposed to k-major so warp lanes (consecutive output cols) are bank-free.
template <bool FINAL>
__global__ __launch_bounds__(1024, 1) void k_congru(
    const float* __restrict__ Wc,  const float* __restrict__ bc,
    const float* __restrict__ Wih, const float* __restrict__ Whh,
    const float* __restrict__ bih, const float* __restrict__ bhh,
    const float* __restrict__ Wl,  const float* __restrict__ bl,
    float* __restrict__ dout) {
    extern __shared__ float sm[];
    const int OC = FINAL ? CC : HH;
    float* sWc  = sm;                 // [k*64 + c], 128x64
    float* sWih = sWc  + FF * HH;     // [k*192 + c'], 64x192
    float* sWhh = sWih + HH * 192;    // [k*192 + c']
    float* sWl  = sWhh + HH * 192;    // [k*OC + j]
    float* sbc  = sWl  + HH * OC;     // 64
    float* sbih = sbc  + HH;          // 192
    float* sbhh = sbih + 192;         // 192
    float* sbl  = sbhh + 192;         // 64 (padded)
    float* xc   = sbl  + HH;          // 16 x 128 (concat; later reused for hnew)
    float* hs   = xc   + 16 * FF;     // 16 x 64
    float* gg   = hs   + 16 * HH;     // 16 x 64 (concat-linear result = GRU x)

    int t = threadIdx.x;
    for (int i = t; i < FF * HH; i += 1024) {
        int r = i >> 7, k = i & 127;
        sWc[k * HH + r] = Wc[i];
    }
    for (int i = t; i < 192 * HH; i += 1024) {
        int r = i / HH, k = i % HH;
        sWih[k * 192 + r] = Wih[i];
        sWhh[k * 192 + r] = Whh[i];
    }
    for (int i = t; i < OC * HH; i += 1024) {
        int r = i / HH, k = i % HH;
        sWl[k * OC + r] = Wl[i];
    }
    if (t < HH) sbc[t] = bc[t];
    if (t >= 256 && t < 256 + 192) sbih[t - 256] = bih[t - 256];
    if (t >= 512 && t < 512 + 192) sbhh[t - 512] = bhh[t - 512];
    if (t >= 768 && t < 768 + OC)  sbl[t - 768]  = bl[t - 768];

    int base = blockIdx.x * 16;
    for (int i = t; i < 16 * HH; i += 1024) {
        int ln = i >> 6, k = i & 63;
        xc[ln * FF + k]      = g_x1[(base + ln) * HH + k];
        xc[ln * FF + 64 + k] = g_x2[(base + ln) * HH + k];
        hs[i]                = g_h0[(base + ln) * HH + k];
    }
    __syncthreads();

    int c = t & 63, ln = t >> 6;

    // concat-linear: gg = [x1|x2] @ Wc^T + bc
    {
        float acc = sbc[c];
        const float* xr = &xc[ln * FF];
#pragma unroll 8
        for (int k = 0; k < FF; k++) acc += xr[k] * sWc[k * HH + c];
        gg[ln * HH + c] = acc;
    }
    __syncthreads();

    // GRU(gg, h0)
    float hnew;
    {
        float ir = sbih[c], iz = sbih[64 + c], inn = sbih[128 + c];
        float hr = sbhh[c], hz = sbhh[64 + c], hn  = sbhh[128 + c];
        const float* xr = &gg[ln * HH];
        const float* hv = &hs[ln * HH];
#pragma unroll 4
        for (int k = 0; k < HH; k++) {
            float xv = xr[k], hw = hv[k];
            const float* wi = &sWih[k * 192 + c];
            const float* wh = &sWhh[k * 192 + c];
            ir += xv * wi[0];  iz += xv * wi[64];  inn += xv * wi[128];
            hr += hw * wh[0];  hz += hw * wh[64];  hn  += hw * wh[128];
        }
        float r = 1.f / (1.f + expf(-(ir + hr)));
        float z = 1.f / (1.f + expf(-(iz + hz)));
        float n = tanhf(inn + r * hn);
        hnew = (1.f - z) * n + z * hv[c];
    }
    // xc no longer read; stash hnew there (sync guarantees con-phase reads done)
    xc[ln * FF + c] = hnew;
    __syncthreads();

    if (!FINAL) {
        float acc = sbl[c];
        const float* xr = &xc[ln * FF];
#pragma unroll 8
        for (int k = 0; k < HH; k++) acc += xr[k] * sWl[k * HH + c];
        g_xmid[(base + ln) * HH + c] = acc;
    } else {
        if (c < CC) {
            float o = sbl[c];
            const float* xr = &xc[ln * FF];
#pragma unroll 8
            for (int k = 0; k < HH; k++) o += xr[k] * sWl[k * CC + c];
            // log_softmax over 16 classes within lanes 0..15
            float m = o;
#pragma unroll
            for (int off = 8; off; off >>= 1)
                m = fmaxf(m, __shfl_xor_sync(0x0000FFFFu, m, off, 16));
            float s = expf(o - m);
#pragma unroll
            for (int off = 8; off; off >>= 1)
                s += __shfl_xor_sync(0x0000FFFFu, s, off, 16);
            dout[(base + ln) * CC + c] = o - (m + logf(s));
        }
    }
}

// ---------------- launch ----------------------------------------------------
static const int SMEM_MID =
    (FF * HH + 2 * HH * 192 + HH * HH + HH + 192 + 192 + HH +
     16 * FF + 16 * HH + 16 * HH) * 4;
static const int SMEM_FIN =
    (FF * HH + 2 * HH * 192 + HH * CC + HH + 192 + 192 + HH +
     16 * FF + 16 * HH + 16 * HH) * 4;

extern "C" void kernel_launch(void* const* d_in, const int* in_sizes, int n_in,
                              void* d_out, int out_size) {
    const float* x       = (const float*)d_in[0];
    const int*   ei      = (const int*)  d_in[1];
    const float* ew      = (const float*)d_in[2];
    const int*   eir     = (const int*)  d_in[3];
    const float* ewr     = (const float*)d_in[4];
    const float* W_first = (const float*)d_in[5];
    const float* b_first = (const float*)d_in[6];
    const float* W_con1  = (const float*)d_in[7];
    const float* b_con1  = (const float*)d_in[8];
    const float* W_con2  = (const float*)d_in[9];
    const float* b_con2  = (const float*)d_in[10];
    const float* W_lin1  = (const float*)d_in[11];
    const float* b_lin1  = (const float*)d_in[12];
    const float* W_out   = (const float*)d_in[13];
    const float* b_out   = (const float*)d_in[14];
    const float* W_ih    = (const float*)d_in[15];
    const float* W_hh    = (const float*)d_in[16];
    const float* b_ih    = (const float*)d_in[17];
    const float* b_hh    = (const float*)d_in[18];
    float* out = (float*)d_out;

    cudaFuncSetAttribute(k_congru<false>,
                         cudaFuncAttributeMaxDynamicSharedMemorySize, SMEM_MID);
    cudaFuncSetAttribute(k_congru<true>,
                         cudaFuncAttributeMaxDynamicSharedMemorySize, SMEM_FIN);

    const int PROP_BLOCKS = (2 * EE) / 8;  // one warp per edge, 8 warps/block

    k_zero<<<1024, 256>>>();
    k_first<<<NN / 8, 512>>>(x, W_first, b_first);
    k_prop<<<PROP_BLOCKS, 256>>>(0, ei, ew, eir, ewr);
    k_congru<false><<<NN / 16, 1024, SMEM_MID>>>(
        W_con1, b_con1, W_ih, W_hh, b_ih, b_hh, W_lin1, b_lin1, nullptr);
    k_zero<<<1024, 256>>>();
    k_prop<<<PROP_BLOCKS, 256>>>(1, ei, ew, eir, ewr);
    k_congru<true><<<NN / 16, 1024, SMEM_FIN>>>(
        W_con2, b_con2, W_ih, W_hh, b_ih, b_hh, W_out, b_out, out);
}

// round 2
// speedup vs baseline: 2.0030x; 2.0030x over previous
#include <cuda_runtime.h>
#include <math.h>

#define NN 100000
#define FF 128
#define HH 64
#define CC 16
#define EE 1000000

// ---------------- scratch (device globals; no allocation allowed) ----------
__device__ __align__(16) float g_h0[NN * HH];
__device__ __align__(16) float g_x1[NN * HH];
__device__ __align__(16) float g_x2[NN * HH];
__device__ __align__(16) float g_xmid[NN * HH];

// ---------------- zero the two scatter buffers ------------------------------
__global__ void k_zero() {
    const int tot = NN * HH / 4;
    float4 z = make_float4(0.f, 0.f, 0.f, 0.f);
    for (int i = blockIdx.x * blockDim.x + threadIdx.x; i < tot;
         i += gridDim.x * blockDim.x) {
        reinterpret_cast<float4*>(g_x1)[i] = z;
        reinterpret_cast<float4*>(g_x2)[i] = z;
    }
}

// ---------------- first linear: h0 = x @ W_first^T + b ----------------------
// 32 nodes/block, 16 threads/node, 4 output cols/thread (LDS.128 weights).
__global__ __launch_bounds__(512) void k_first(const float* __restrict__ x,
                                               const float* __restrict__ W,
                                               const float* __restrict__ b) {
    __shared__ float Ws[FF * HH];   // Ws[f*64 + h] = W[h][f]
    __shared__ float xs[32 * FF];
    int t = threadIdx.x;
    for (int i = t; i < HH * FF; i += 512) {
        int h = i >> 7, f = i & 127;
        Ws[f * HH + h] = W[i];
    }
    int base = blockIdx.x * 32;
    for (int i = t; i < 32 * FF / 4; i += 512)
        reinterpret_cast<float4*>(xs)[i] =
            reinterpret_cast<const float4*>(x + base * FF)[i];
    __syncthreads();

    int tq = t & 15, ln = t >> 4;
    int c = tq * 4;
    float4 acc = *reinterpret_cast<const float4*>(b + c);
    const float* xr = &xs[ln * FF];
#pragma unroll 8
    for (int f = 0; f < FF; f++) {
        float xv = xr[f];
        float4 wv = *reinterpret_cast<const float4*>(&Ws[f * HH + c]);
        acc.x += xv * wv.x; acc.y += xv * wv.y;
        acc.z += xv * wv.z; acc.w += xv * wv.w;
    }
    *reinterpret_cast<float4*>(&g_h0[(base + ln) * HH + c]) = acc;
}

// ---------------- edge propagation: 16 lanes/edge, vector RED ---------------
// slot < E  : forward edges  -> g_x1
// slot >= E : reverse edges  -> g_x2
__global__ __launch_bounds__(256) void k_prop(int use_mid,
                                              const int* __restrict__ ei1,
                                              const float* __restrict__ ew1,
                                              const int* __restrict__ ei2,
                                              const float* __restrict__ ew2) {
    const float* xin = use_mid ? g_xmid : g_h0;
    int slot = blockIdx.x * 16 + (threadIdx.x >> 4);
    int l16 = threadIdx.x & 15;

    const int* ei;
    const float* ew;
    float* out;
    int e;
    if (slot < EE) { e = slot;      ei = ei1; ew = ew1; out = g_x1; }
    else           { e = slot - EE; ei = ei2; ew = ew2; out = g_x2; }

    int src = __ldg(ei + e);
    int dst = __ldg(ei + EE + e);
    float w = __ldg(ew + e);

    float4 v = *reinterpret_cast<const float4*>(xin + src * HH + l16 * 4);
    float* p = out + dst * HH + l16 * 4;
    asm volatile("red.global.add.v4.f32 [%0], {%1, %2, %3, %4};"
                 :: "l"(p), "f"(v.x * w), "f"(v.y * w),
                    "f"(v.z * w), "f"(v.w * w)
                 : "memory");
}

// ---------------- fused concat-linear + GRU + (lin1 | out+log_softmax) ------
// 64 nodes/block, 16 threads/node, 4 cols/thread. Weights k-major in smem.
template <bool FINAL>
__global__ __launch_bounds__(1024, 1) void k_congru(
    const float* __restrict__ Wc,  const float* __restrict__ bc,
    const float* __restrict__ Wih, const float* __restrict__ Whh,
    const float* __restrict__ bih, const float* __restrict__ bhh,
    const float* __restrict__ Wl,  const float* __restrict__ bl,
    float* __restrict__ dout) {
    extern __shared__ float sm[];
    const int OC = FINAL ? CC : HH;
    float* sWc  = sm;                 // [k*64 + c], 128x64
    float* sWih = sWc  + FF * HH;     // [k*192 + c'], 64x192
    float* sWhh = sWih + HH * 192;    // [k*192 + c']
    float* sWl  = sWhh + HH * 192;    // [k*OC + j]
    float* sbc  = sWl  + HH * OC;     // 64
    float* sbih = sbc  + HH;          // 192
    float* sbhh = sbih + 192;         // 192
    float* sbl  = sbhh + 192;         // OC (padded to 64)
    float* xc   = sbl  + HH;          // 64 x 128 (concat; later reused: hnew)
    float* hs   = xc   + 64 * FF;     // 64 x 64
    float* gg   = hs   + 64 * HH;     // 64 x 64

    int t = threadIdx.x;
    for (int i = t; i < FF * HH; i += 1024) {
        int r = i >> 7, k = i & 127;
        sWc[k * HH + r] = Wc[i];
    }
    for (int i = t; i < 192 * HH; i += 1024) {
        int r = i / HH, k = i % HH;
        sWih[k * 192 + r] = Wih[i];
        sWhh[k * 192 + r] = Whh[i];
    }
    for (int i = t; i < OC * HH; i += 1024) {
        int r = i / HH, k = i % HH;
        sWl[k * OC + r] = Wl[i];
    }
    if (t < HH) sbc[t] = bc[t];
    if (t >= 256 && t < 256 + 192) sbih[t - 256] = bih[t - 256];
    if (t >= 512 && t < 512 + 192) sbhh[t - 512] = bhh[t - 512];
    if (t >= 768 && t < 768 + OC)  sbl[t - 768]  = bl[t - 768];

    int base = blockIdx.x * 64;
    {
        // 1024 threads load 64 nodes x 16 float4 per buffer
        int ln = t >> 4, k4 = (t & 15) * 4;
        int node = base + ln;
        float4 z = make_float4(0.f, 0.f, 0.f, 0.f);
        float4 a = z, bb = z, hvec = z;
        if (node < NN) {
            a    = *reinterpret_cast<const float4*>(&g_x1[node * HH + k4]);
            bb   = *reinterpret_cast<const float4*>(&g_x2[node * HH + k4]);
            hvec = *reinterpret_cast<const float4*>(&g_h0[node * HH + k4]);
        }
        *reinterpret_cast<float4*>(&xc[ln * FF + k4])      = a;
        *reinterpret_cast<float4*>(&xc[ln * FF + 64 + k4]) = bb;
        *reinterpret_cast<float4*>(&hs[ln * HH + k4])      = hvec;
    }
    __syncthreads();

    int tq = t & 15, ln = t >> 4;
    int c = tq * 4;
    int node = base + ln;

    // concat-linear: gg = [x1|x2] @ Wc^T + bc
    {
        float4 acc = *reinterpret_cast<const float4*>(&sbc[c]);
        const float* xr = &xc[ln * FF];
#pragma unroll 8
        for (int k = 0; k < FF; k++) {
            float xv = xr[k];
            float4 wv = *reinterpret_cast<const float4*>(&sWc[k * HH + c]);
            acc.x += xv * wv.x; acc.y += xv * wv.y;
            acc.z += xv * wv.z; acc.w += xv * wv.w;
        }
        *reinterpret_cast<float4*>(&gg[ln * HH + c]) = acc;
    }
    __syncthreads();

    // GRU(gg, h0)
    float4 hnew;
    {
        float4 ar = *reinterpret_cast<const float4*>(&sbih[c]);
        float4 az = *reinterpret_cast<const float4*>(&sbih[64 + c]);
        float4 an = *reinterpret_cast<const float4*>(&sbih[128 + c]);
        float4 hr = *reinterpret_cast<const float4*>(&sbhh[c]);
        float4 hz = *reinterpret_cast<const float4*>(&sbhh[64 + c]);
        float4 hn = *reinterpret_cast<const float4*>(&sbhh[128 + c]);
        const float* xr = &gg[ln * HH];
        const float* hv = &hs[ln * HH];
#pragma unroll 2
        for (int k = 0; k < HH; k++) {
            float xv = xr[k], hw = hv[k];
            float4 wir = *reinterpret_cast<const float4*>(&sWih[k * 192 + c]);
            float4 wiz = *reinterpret_cast<const float4*>(&sWih[k * 192 + 64 + c]);
            float4 win = *reinterpret_cast<const float4*>(&sWih[k * 192 + 128 + c]);
            float4 whr = *reinterpret_cast<const float4*>(&sWhh[k * 192 + c]);
            float4 whz = *reinterpret_cast<const float4*>(&sWhh[k * 192 + 64 + c]);
            float4 whn = *reinterpret_cast<const float4*>(&sWhh[k * 192 + 128 + c]);
            ar.x += xv * wir.x; ar.y += xv * wir.y; ar.z += xv * wir.z; ar.w += xv * wir.w;
            az.x += xv * wiz.x; az.y += xv * wiz.y; az.z += xv * wiz.z; az.w += xv * wiz.w;
            an.x += xv * win.x; an.y += xv * win.y; an.z += xv * win.z; an.w += xv * win.w;
            hr.x += hw * whr.x; hr.y += hw * whr.y; hr.z += hw * whr.z; hr.w += hw * whr.w;
            hz.x += hw * whz.x; hz.y += hw * whz.y; hz.z += hw * whz.z; hz.w += hw * whz.w;
            hn.x += hw * whn.x; hn.y += hw * whn.y; hn.z += hw * whn.z; hn.w += hw * whn.w;
        }
        float ho0 = hv[c], ho1 = hv[c + 1], ho2 = hv[c + 2], ho3 = hv[c + 3];
        {
            float r = 1.f / (1.f + __expf(-(ar.x + hr.x)));
            float z = 1.f / (1.f + __expf(-(az.x + hz.x)));
            float n = tanhf(an.x + r * hn.x);
            hnew.x = (1.f - z) * n + z * ho0;
        }
        {
            float r = 1.f / (1.f + __expf(-(ar.y + hr.y)));
            float z = 1.f / (1.f + __expf(-(az.y + hz.y)));
            float n = tanhf(an.y + r * hn.y);
            hnew.y = (1.f - z) * n + z * ho1;
        }
        {
            float r = 1.f / (1.f + __expf(-(ar.z + hr.z)));
            float z = 1.f / (1.f + __expf(-(az.z + hz.z)));
            float n = tanhf(an.z + r * hn.z);
            hnew.z = (1.f - z) * n + z * ho2;
        }
        {
            float r = 1.f / (1.f + __expf(-(ar.w + hr.w)));
            float z = 1.f / (1.f + __expf(-(az.w + hz.w)));
            float n = tanhf(an.w + r * hn.w);
            hnew.w = (1.f - z) * n + z * ho3;
        }
    }
    // xc no longer read; stash hnew there
    *reinterpret_cast<float4*>(&xc[ln * FF + c]) = hnew;
    __syncthreads();

    if (!FINAL) {
        float4 acc = *reinterpret_cast<const float4*>(&sbl[c]);
        const float* xr = &xc[ln * FF];
#pragma unroll 8
        for (int k = 0; k < HH; k++) {
            float xv = xr[k];
            float4 wv = *reinterpret_cast<const float4*>(&sWl[k * HH + c]);
            acc.x += xv * wv.x; acc.y += xv * wv.y;
            acc.z += xv * wv.z; acc.w += xv * wv.w;
        }
        if (node < NN)
            *reinterpret_cast<float4*>(&g_xmid[node * HH + c]) = acc;
    } else {
        // 16 threads per node, 1 class per thread
        float o = sbl[tq];
        const float* xr = &xc[ln * FF];
#pragma unroll 8
        for (int k = 0; k < HH; k++) o += xr[k] * sWl[k * CC + tq];
        float m = o;
#pragma unroll
        for (int off = 8; off; off >>= 1)
            m = fmaxf(m, __shfl_xor_sync(0xFFFFFFFFu, m, off, 16));
        float s = expf(o - m);
#pragma unroll
        for (int off = 8; off; off >>= 1)
            s += __shfl_xor_sync(0xFFFFFFFFu, s, off, 16);
        if (node < NN) dout[node * CC + tq] = o - (m + logf(s));
    }
}

// ---------------- launch ----------------------------------------------------
static const int SMEM_MID =
    (FF * HH + 2 * HH * 192 + HH * HH + HH + 192 + 192 + HH +
     64 * FF + 64 * HH + 64 * HH) * 4;
static const int SMEM_FIN =
    (FF * HH + 2 * HH * 192 + HH * CC + HH + 192 + 192 + HH +
     64 * FF + 64 * HH + 64 * HH) * 4;

extern "C" void kernel_launch(void* const* d_in, const int* in_sizes, int n_in,
                              void* d_out, int out_size) {
    const float* x       = (const float*)d_in[0];
    const int*   ei      = (const int*)  d_in[1];
    const float* ew      = (const float*)d_in[2];
    const int*   eir     = (const int*)  d_in[3];
    const float* ewr     = (const float*)d_in[4];
    const float* W_first = (const float*)d_in[5];
    const float* b_first = (const float*)d_in[6];
    const float* W_con1  = (const float*)d_in[7];
    const float* b_con1  = (const float*)d_in[8];
    const float* W_con2  = (const float*)d_in[9];
    const float* b_con2  = (const float*)d_in[10];
    const float* W_lin1  = (const float*)d_in[11];
    const float* b_lin1  = (const float*)d_in[12];
    const float* W_out   = (const float*)d_in[13];
    const float* b_out   = (const float*)d_in[14];
    const float* W_ih    = (const float*)d_in[15];
    const float* W_hh    = (const float*)d_in[16];
    const float* b_ih    = (const float*)d_in[17];
    const float* b_hh    = (const float*)d_in[18];
    float* out = (float*)d_out;

    cudaFuncSetAttribute(k_congru<false>,
                         cudaFuncAttributeMaxDynamicSharedMemorySize, SMEM_MID);
    cudaFuncSetAttribute(k_congru<true>,
                         cudaFuncAttributeMaxDynamicSharedMemorySize, SMEM_FIN);

    const int PROP_BLOCKS = (2 * EE) / 16;  // 16 lanes/edge, 16 edges/block
    const int CONGRU_BLOCKS = (NN + 63) / 64;

    k_zero<<<1024, 256>>>();
    k_first<<<NN / 32, 512>>>(x, W_first, b_first);
    k_prop<<<PROP_BLOCKS, 256>>>(0, ei, ew, eir, ewr);
    k_congru<false><<<CONGRU_BLOCKS, 1024, SMEM_MID>>>(
        W_con1, b_con1, W_ih, W_hh, b_ih, b_hh, W_lin1, b_lin1, nullptr);
    k_zero<<<1024, 256>>>();
    k_prop<<<PROP_BLOCKS, 256>>>(1, ei, ew, eir, ewr);
    k_congru<true><<<CONGRU_BLOCKS, 1024, SMEM_FIN>>>(
        W_con2, b_con2, W_ih, W_hh, b_ih, b_hh, W_out, b_out, out);
}

// round 3
// speedup vs baseline: 6.0392x; 3.0151x over previous
#include <cuda_runtime.h>
#include <math.h>
#include <stdint.h>

#define NN 100000
#define FF 128
#define HH 64
#define CC 16
#define EE 1000000
#define KP128 132
#define KP64 68

// ---------------- scratch ----------------------------------------------------
__device__ __align__(16) float g_h0[NN * HH];
__device__ __align__(16) float g_ghh[NN * 192];
__device__ __align__(16) float g_x1[NN * HH];
__device__ __align__(16) float g_x2[NN * HH];
__device__ __align__(16) float g_xmid[NN * HH];

// ---------------- tf32 mma helpers ------------------------------------------
__device__ __forceinline__ uint32_t f2tf(float f) {
    uint32_t u;
    asm("cvt.rna.tf32.f32 %0, %1;" : "=r"(u) : "f"(f));
    return u;
}
__device__ __forceinline__ void mma8(float4& d, uint32_t a0, uint32_t a1,
                                     uint32_t a2, uint32_t a3,
                                     uint32_t b0, uint32_t b1) {
    asm volatile(
        "mma.sync.aligned.m16n8k8.row.col.f32.tf32.tf32.f32 "
        "{%0,%1,%2,%3},{%4,%5,%6,%7},{%8,%9},{%0,%1,%2,%3};"
        : "+f"(d.x), "+f"(d.y), "+f"(d.z), "+f"(d.w)
        : "r"(a0), "r"(a1), "r"(a2), "r"(a3), "r"(b0), "r"(b1));
}

__device__ __forceinline__ float sigf(float x) {
    return 1.f / (1.f + __expf(-x));
}

// ---------------- zero the two scatter buffers -------------------------------
__global__ void k_zero() {
    const int tot = NN * HH / 4;
    float4 z = make_float4(0.f, 0.f, 0.f, 0.f);
    for (int i = blockIdx.x * blockDim.x + threadIdx.x; i < tot;
         i += gridDim.x * blockDim.x) {
        reinterpret_cast<float4*>(g_x1)[i] = z;
        reinterpret_cast<float4*>(g_x2)[i] = z;
    }
}

// ---------------- k_first: h0 = x @ Wf^T + b (tf32 mma) ----------------------
// 128 nodes/block, 512 threads. Warp w: rows (w%8)*16, cols (w/8)*32 (4 tiles).
__global__ __launch_bounds__(512, 1) void k_first(const float* __restrict__ x,
                                                  const float* __restrict__ W,
                                                  const float* __restrict__ b) {
    extern __shared__ uint32_t sm[];
    uint32_t* sA = sm;                   // 128 x 132
    uint32_t* sB = sA + 128 * KP128;     // 64 x 132
    __shared__ float sb[64];
    int t = threadIdx.x;
    int base = blockIdx.x * 128;

    for (int i = t; i < 128 * 32; i += 512) {
        int node = i >> 5, q = i & 31;
        float4 v = make_float4(0.f, 0.f, 0.f, 0.f);
        if (base + node < NN)
            v = *(const float4*)(x + (base + node) * FF + q * 4);
        uint32_t* d = sA + node * KP128 + q * 4;
        d[0] = f2tf(v.x); d[1] = f2tf(v.y); d[2] = f2tf(v.z); d[3] = f2tf(v.w);
    }
    for (int i = t; i < 64 * 32; i += 512) {
        int o = i >> 5, q = i & 31;
        float4 v = *(const float4*)(W + o * FF + q * 4);
        uint32_t* d = sB + o * KP128 + q * 4;
        d[0] = f2tf(v.x); d[1] = f2tf(v.y); d[2] = f2tf(v.z); d[3] = f2tf(v.w);
    }
    if (t < 64) sb[t] = b[t];
    __syncthreads();

    int w = t >> 5, lane = t & 31, g = lane >> 2, tig = lane & 3;
    int r0 = (w & 7) * 16, cb = (w >> 3) * 32;
    float4 acc[4] = {};
#pragma unroll 4
    for (int ks = 0; ks < 16; ks++) {
        int ko = ks * 8;
        uint32_t a0 = sA[(r0 + g) * KP128 + ko + tig];
        uint32_t a1 = sA[(r0 + g + 8) * KP128 + ko + tig];
        uint32_t a2 = sA[(r0 + g) * KP128 + ko + tig + 4];
        uint32_t a3 = sA[(r0 + g + 8) * KP128 + ko + tig + 4];
#pragma unroll
        for (int nt = 0; nt < 4; nt++) {
            int o = cb + nt * 8 + g;
            mma8(acc[nt], a0, a1, a2, a3,
                 sB[o * KP128 + ko + tig], sB[o * KP128 + ko + tig + 4]);
        }
    }
#pragma unroll
    for (int nt = 0; nt < 4; nt++) {
        int c = cb + nt * 8 + tig * 2;
        int n1 = base + r0 + g, n2 = n1 + 8;
        if (n1 < NN)
            *(float2*)(g_h0 + n1 * HH + c) =
                make_float2(acc[nt].x + sb[c], acc[nt].y + sb[c + 1]);
        if (n2 < NN)
            *(float2*)(g_h0 + n2 * HH + c) =
                make_float2(acc[nt].z + sb[c], acc[nt].w + sb[c + 1]);
    }
}

// ---------------- k_ghh: ghh = h0 @ Whh^T + bhh (shared by both layers) ------
__global__ __launch_bounds__(512, 1) void k_ghh(const float* __restrict__ W,
                                                const float* __restrict__ b) {
    extern __shared__ uint32_t sm[];
    uint32_t* sA = sm;                 // 128 x 68
    uint32_t* sB = sA + 128 * KP64;    // 192 x 68
    __shared__ float sb[192];
    int t = threadIdx.x;
    int base = blockIdx.x * 128;

    for (int i = t; i < 128 * 16; i += 512) {
        int node = i >> 4, q = i & 15;
        float4 v = make_float4(0.f, 0.f, 0.f, 0.f);
        if (base + node < NN)
            v = *(const float4*)(g_h0 + (base + node) * HH + q * 4);
        uint32_t* d = sA + node * KP64 + q * 4;
        d[0] = f2tf(v.x); d[1] = f2tf(v.y); d[2] = f2tf(v.z); d[3] = f2tf(v.w);
    }
    for (int i = t; i < 192 * 16; i += 512) {
        int o = i >> 4, q = i & 15;
        float4 v = *(const float4*)(W + o * HH + q * 4);
        uint32_t* d = sB + o * KP64 + q * 4;
        d[0] = f2tf(v.x); d[1] = f2tf(v.y); d[2] = f2tf(v.z); d[3] = f2tf(v.w);
    }
    if (t < 192) sb[t] = b[t];
    __syncthreads();

    int w = t >> 5, lane = t & 31, g = lane >> 2, tig = lane & 3;
    int r0 = (w & 7) * 16, cb = (w >> 3) * 96;  // 12 n-tiles per warp
    float4 acc[12] = {};
    for (int ks = 0; ks < 8; ks++) {
        int ko = ks * 8;
        uint32_t a0 = sA[(r0 + g) * KP64 + ko + tig];
        uint32_t a1 = sA[(r0 + g + 8) * KP64 + ko + tig];
        uint32_t a2 = sA[(r0 + g) * KP64 + ko + tig + 4];
        uint32_t a3 = sA[(r0 + g + 8) * KP64 + ko + tig + 4];
#pragma unroll
        for (int nt = 0; nt < 12; nt++) {
            int o = cb + nt * 8 + g;
            mma8(acc[nt], a0, a1, a2, a3,
                 sB[o * KP64 + ko + tig], sB[o * KP64 + ko + tig + 4]);
        }
    }
#pragma unroll
    for (int nt = 0; nt < 12; nt++) {
        int c = cb + nt * 8 + tig * 2;
        int n1 = base + r0 + g, n2 = n1 + 8;
        if (n1 < NN)
            *(float2*)(g_ghh + n1 * 192 + c) =
                make_float2(acc[nt].x + sb[c], acc[nt].y + sb[c + 1]);
        if (n2 < NN)
            *(float2*)(g_ghh + n2 * 192 + c) =
                make_float2(acc[nt].z + sb[c], acc[nt].w + sb[c + 1]);
    }
}

// ---------------- edge propagation: 16 lanes/edge, vector RED ----------------
__global__ __launch_bounds__(256) void k_prop(int use_mid,
                                              const int* __restrict__ ei1,
                                              const float* __restrict__ ew1,
                                              const int* __restrict__ ei2,
                                              const float* __restrict__ ew2) {
    const float* xin = use_mid ? g_xmid : g_h0;
    int slot = blockIdx.x * 16 + (threadIdx.x >> 4);
    int l16 = threadIdx.x & 15;

    const int* ei;
    const float* ew;
    float* out;
    int e;
    if (slot < EE) { e = slot;      ei = ei1; ew = ew1; out = g_x1; }
    else           { e = slot - EE; ei = ei2; ew = ew2; out = g_x2; }

    int src = __ldg(ei + e);
    int dst = __ldg(ei + EE + e);
    float w = __ldg(ew + e);

    float4 v = *reinterpret_cast<const float4*>(xin + src * HH + l16 * 4);
    float* p = out + dst * HH + l16 * 4;
    asm volatile("red.global.add.v4.f32 [%0], {%1, %2, %3, %4};"
                 :: "l"(p), "f"(v.x * w), "f"(v.y * w),
                    "f"(v.z * w), "f"(v.w * w)
                 : "memory");
}

// ---------------- fused concat-linear + GRU + (lin | out+logsoftmax) --------
// 128 nodes/block, 512 threads. tf32 mma throughout.
// smem word offsets:
#define O_A    0                         // 128x132 concat input (tf32)
#define O_WC   (O_A + 128 * KP128)       // 64x132
#define O_WIH  (O_WC + 64 * KP128)       // 192x68
#define O_WL   (O_WIH + 192 * KP64)      // 64x68
#define O_G    (O_WL + 64 * KP64)        // 128x68 gg / hnew (tf32)
#define O_BC   (O_G + 128 * KP64)        // 64
#define O_BIH  (O_BC + 64)               // 192
#define O_BL   (O_BIH + 192)             // 64
#define CG_WORDS (O_BL + 64)

template <bool FINAL>
__global__ __launch_bounds__(512, 1) void k_congru(
    const float* __restrict__ Wc,  const float* __restrict__ bc,
    const float* __restrict__ Wih, const float* __restrict__ bih,
    const float* __restrict__ Wl,  const float* __restrict__ bl,
    float* __restrict__ dout) {
    extern __shared__ uint32_t sm[];
    uint32_t* sA   = sm + O_A;
    uint32_t* sWc  = sm + O_WC;
    uint32_t* sWih = sm + O_WIH;
    uint32_t* sWl  = sm + O_WL;
    uint32_t* sG   = sm + O_G;
    float* sbc  = (float*)(sm + O_BC);
    float* sbih = (float*)(sm + O_BIH);
    float* sbl  = (float*)(sm + O_BL);
    const int OC = FINAL ? CC : HH;

    int t = threadIdx.x;
    int base = blockIdx.x * 128;

    // ---- stage inputs/weights (tf32) ----
    for (int i = t; i < 128 * 16; i += 512) {
        int node = i >> 4, q = i & 15;
        int n = base + node;
        float4 v1 = make_float4(0.f, 0.f, 0.f, 0.f), v2 = v1;
        if (n < NN) {
            v1 = *(const float4*)(g_x1 + n * HH + q * 4);
            v2 = *(const float4*)(g_x2 + n * HH + q * 4);
        }
        uint32_t* d1 = sA + node * KP128 + q * 4;
        uint32_t* d2 = d1 + 64;
        d1[0] = f2tf(v1.x); d1[1] = f2tf(v1.y); d1[2] = f2tf(v1.z); d1[3] = f2tf(v1.w);
        d2[0] = f2tf(v2.x); d2[1] = f2tf(v2.y); d2[2] = f2tf(v2.z); d2[3] = f2tf(v2.w);
    }
    for (int i = t; i < 64 * 32; i += 512) {
        int o = i >> 5, q = i & 31;
        float4 v = *(const float4*)(Wc + o * FF + q * 4);
        uint32_t* d = sWc + o * KP128 + q * 4;
        d[0] = f2tf(v.x); d[1] = f2tf(v.y); d[2] = f2tf(v.z); d[3] = f2tf(v.w);
    }
    for (int i = t; i < 192 * 16; i += 512) {
        int o = i >> 4, q = i & 15;
        float4 v = *(const float4*)(Wih + o * HH + q * 4);
        uint32_t* d = sWih + o * KP64 + q * 4;
        d[0] = f2tf(v.x); d[1] = f2tf(v.y); d[2] = f2tf(v.z); d[3] = f2tf(v.w);
    }
    for (int i = t; i < OC * 16; i += 512) {
        int o = i >> 4, q = i & 15;
        float4 v = *(const float4*)(Wl + o * HH + q * 4);
        uint32_t* d = sWl + o * KP64 + q * 4;
        d[0] = f2tf(v.x); d[1] = f2tf(v.y); d[2] = f2tf(v.z); d[3] = f2tf(v.w);
    }
    if (t < 64)  sbc[t]  = bc[t];
    if (t < 192) sbih[t] = bih[t];
    if (t < OC)  sbl[t]  = bl[t];
    __syncthreads();

    int w = t >> 5, lane = t & 31, g = lane >> 2, tig = lane & 3;
    int r0 = (w & 7) * 16, cb = (w >> 3) * 32;

    // ---- phase 1: gg = [x1|x2] @ Wc^T + bc  (K=128) ----
    {
        float4 acc[4] = {};
#pragma unroll 4
        for (int ks = 0; ks < 16; ks++) {
            int ko = ks * 8;
            uint32_t a0 = sA[(r0 + g) * KP128 + ko + tig];
            uint32_t a1 = sA[(r0 + g + 8) * KP128 + ko + tig];
            uint32_t a2 = sA[(r0 + g) * KP128 + ko + tig + 4];
            uint32_t a3 = sA[(r0 + g + 8) * KP128 + ko + tig + 4];
#pragma unroll
            for (int nt = 0; nt < 4; nt++) {
                int o = cb + nt * 8 + g;
                mma8(acc[nt], a0, a1, a2, a3,
                     sWc[o * KP128 + ko + tig], sWc[o * KP128 + ko + tig + 4]);
            }
        }
        __syncthreads();
#pragma unroll
        for (int nt = 0; nt < 4; nt++) {
            int c = cb + nt * 8 + tig * 2;
            sG[(r0 + g) * KP64 + c]         = f2tf(acc[nt].x + sbc[c]);
            sG[(r0 + g) * KP64 + c + 1]     = f2tf(acc[nt].y + sbc[c + 1]);
            sG[(r0 + g + 8) * KP64 + c]     = f2tf(acc[nt].z + sbc[c]);
            sG[(r0 + g + 8) * KP64 + c + 1] = f2tf(acc[nt].w + sbc[c + 1]);
        }
    }
    __syncthreads();

    // ---- phase 2: gi = gg @ Wih^T (K=64, 3 gates x 4 n-tiles per warp) ----
    float4 d2[3][4];
#pragma unroll
    for (int gt = 0; gt < 3; gt++)
#pragma unroll
        for (int nt = 0; nt < 4; nt++) d2[gt][nt] = make_float4(0.f, 0.f, 0.f, 0.f);
    for (int ks = 0; ks < 8; ks++) {
        int ko = ks * 8;
        uint32_t a0 = sG[(r0 + g) * KP64 + ko + tig];
        uint32_t a1 = sG[(r0 + g + 8) * KP64 + ko + tig];
        uint32_t a2 = sG[(r0 + g) * KP64 + ko + tig + 4];
        uint32_t a3 = sG[(r0 + g + 8) * KP64 + ko + tig + 4];
#pragma unroll
        for (int gt = 0; gt < 3; gt++)
#pragma unroll
            for (int nt = 0; nt < 4; nt++) {
                int o = gt * 64 + cb + nt * 8 + g;
                mma8(d2[gt][nt], a0, a1, a2, a3,
                     sWih[o * KP64 + ko + tig], sWih[o * KP64 + ko + tig + 4]);
            }
    }

    // ---- phase 3: GRU elementwise (ghh + bhh precomputed in g_ghh) ----
    float hn[4][4];
#pragma unroll
    for (int nt = 0; nt < 4; nt++) {
        int c = cb + nt * 8 + tig * 2;
#pragma unroll
        for (int half = 0; half < 2; half++) {
            int node = base + r0 + g + half * 8;
            float vr0 = half ? d2[0][nt].z : d2[0][nt].x;
            float vr1 = half ? d2[0][nt].w : d2[0][nt].y;
            float vz0 = half ? d2[1][nt].z : d2[1][nt].x;
            float vz1 = half ? d2[1][nt].w : d2[1][nt].y;
            float vn0 = half ? d2[2][nt].z : d2[2][nt].x;
            float vn1 = half ? d2[2][nt].w : d2[2][nt].y;
            float o0 = 0.f, o1 = 0.f;
            if (node < NN) {
                float2 gr = *(const float2*)(g_ghh + node * 192 + c);
                float2 gz = *(const float2*)(g_ghh + node * 192 + 64 + c);
                float2 gn = *(const float2*)(g_ghh + node * 192 + 128 + c);
                float2 h  = *(const float2*)(g_h0 + node * HH + c);
                float r = sigf(vr0 + sbih[c] + gr.x);
                float z = sigf(vz0 + sbih[64 + c] + gz.x);
                float n = tanhf(vn0 + sbih[128 + c] + r * gn.x);
                o0 = (1.f - z) * n + z * h.x;
                r = sigf(vr1 + sbih[c + 1] + gr.y);
                z = sigf(vz1 + sbih[64 + c + 1] + gz.y);
                n = tanhf(vn1 + sbih[128 + c + 1] + r * gn.y);
                o1 = (1.f - z) * n + z * h.y;
            }
            hn[nt][half * 2] = o0;
            hn[nt][half * 2 + 1] = o1;
        }
    }
    __syncthreads();
#pragma unroll
    for (int nt = 0; nt < 4; nt++) {
        int c = cb + nt * 8 + tig * 2;
        sG[(r0 + g) * KP64 + c]         = f2tf(hn[nt][0]);
        sG[(r0 + g) * KP64 + c + 1]     = f2tf(hn[nt][1]);
        sG[(r0 + g + 8) * KP64 + c]     = f2tf(hn[nt][2]);
        sG[(r0 + g + 8) * KP64 + c + 1] = f2tf(hn[nt][3]);
    }
    __syncthreads();

    // ---- phase 4: output GEMM (K=64) ----
    if (!FINAL) {
        float4 acc[4] = {};
        for (int ks = 0; ks < 8; ks++) {
            int ko = ks * 8;
            uint32_t a0 = sG[(r0 + g) * KP64 + ko + tig];
            uint32_t a1 = sG[(r0 + g + 8) * KP64 + ko + tig];
            uint32_t a2 = sG[(r0 + g) * KP64 + ko + tig + 4];
            uint32_t a3 = sG[(r0 + g + 8) * KP64 + ko + tig + 4];
#pragma unroll
            for (int nt = 0; nt < 4; nt++) {
                int o = cb + nt * 8 + g;
                mma8(acc[nt], a0, a1, a2, a3,
                     sWl[o * KP64 + ko + tig], sWl[o * KP64 + ko + tig + 4]);
            }
        }
#pragma unroll
        for (int nt = 0; nt < 4; nt++) {
            int c = cb + nt * 8 + tig * 2;
            int n1 = base + r0 + g, n2 = n1 + 8;
            if (n1 < NN)
                *(float2*)(g_xmid + n1 * HH + c) =
                    make_float2(acc[nt].x + sbl[c], acc[nt].y + sbl[c + 1]);
            if (n2 < NN)
                *(float2*)(g_xmid + n2 * HH + c) =
                    make_float2(acc[nt].z + sbl[c], acc[nt].w + sbl[c + 1]);
        }
    } else {
        float4 acc = make_float4(0.f, 0.f, 0.f, 0.f);
        int c0f = (w >> 3) * 8;
        for (int ks = 0; ks < 8; ks++) {
            int ko = ks * 8;
            uint32_t a0 = sG[(r0 + g) * KP64 + ko + tig];
            uint32_t a1 = sG[(r0 + g + 8) * KP64 + ko + tig];
            uint32_t a2 = sG[(r0 + g) * KP64 + ko + tig + 4];
            uint32_t a3 = sG[(r0 + g + 8) * KP64 + ko + tig + 4];
            int o = c0f + g;
            mma8(acc, a0, a1, a2, a3,
                 sWl[o * KP64 + ko + tig], sWl[o * KP64 + ko + tig + 4]);
        }
        float* ly = (float*)sWc;  // dead after phase 1; 128x17 fits
        int c = c0f + tig * 2;
        ly[(r0 + g) * 17 + c]         = acc.x + sbl[c];
        ly[(r0 + g) * 17 + c + 1]     = acc.y + sbl[c + 1];
        ly[(r0 + g + 8) * 17 + c]     = acc.z + sbl[c];
        ly[(r0 + g + 8) * 17 + c + 1] = acc.w + sbl[c + 1];
        __syncthreads();
        if (t < 128) {
            int node = base + t;
            if (node < NN) {
                float m = -1e30f;
#pragma unroll
                for (int cc = 0; cc < 16; cc++) m = fmaxf(m, ly[t * 17 + cc]);
                float s = 0.f;
#pragma unroll
                for (int cc = 0; cc < 16; cc++) s += expf(ly[t * 17 + cc] - m);
                float l = m + logf(s);
#pragma unroll
                for (int cc = 0; cc < 16; cc++)
                    dout[node * CC + cc] = ly[t * 17 + cc] - l;
            }
        }
    }
}

// ---------------- launch -----------------------------------------------------
extern "C" void kernel_launch(void* const* d_in, const int* in_sizes, int n_in,
                              void* d_out, int out_size) {
    const float* x       = (const float*)d_in[0];
    const int*   ei      = (const int*)  d_in[1];
    const float* ew      = (const float*)d_in[2];
    const int*   eir     = (const int*)  d_in[3];
    const float* ewr     = (const float*)d_in[4];
    const float* W_first = (const float*)d_in[5];
    const float* b_first = (const float*)d_in[6];
    const float* W_con1  = (const float*)d_in[7];
    const float* b_con1  = (const float*)d_in[8];
    const float* W_con2  = (const float*)d_in[9];
    const float* b_con2  = (const float*)d_in[10];
    const float* W_lin1  = (const float*)d_in[11];
    const float* b_lin1  = (const float*)d_in[12];
    const float* W_out   = (const float*)d_in[13];
    const float* b_out   = (const float*)d_in[14];
    const float* W_ih    = (const float*)d_in[15];
    const float* W_hh    = (const float*)d_in[16];
    const float* b_ih    = (const float*)d_in[17];
    const float* b_hh    = (const float*)d_in[18];
    float* out = (float*)d_out;

    const int SM_FIRST = (128 * KP128 + 64 * KP128) * 4;
    const int SM_GHH   = (128 * KP64 + 192 * KP64) * 4;
    const int SM_CG    = CG_WORDS * 4;

    cudaFuncSetAttribute(k_first, cudaFuncAttributeMaxDynamicSharedMemorySize, SM_FIRST);
    cudaFuncSetAttribute(k_ghh,   cudaFuncAttributeMaxDynamicSharedMemorySize, SM_GHH);
    cudaFuncSetAttribute(k_congru<false>,
                         cudaFuncAttributeMaxDynamicSharedMemorySize, SM_CG);
    cudaFuncSetAttribute(k_congru<true>,
                         cudaFuncAttributeMaxDynamicSharedMemorySize, SM_CG);

    const int NB = (NN + 127) / 128;           // 782
    const int PROP_BLOCKS = (2 * EE) / 16;     // 16 lanes/edge, 16 edges/block

    k_zero<<<1024, 256>>>();
    k_first<<<NB, 512, SM_FIRST>>>(x, W_first, b_first);
    k_ghh<<<NB, 512, SM_GHH>>>(W_hh, b_hh);
    k_prop<<<PROP_BLOCKS, 256>>>(0, ei, ew, eir, ewr);
    k_congru<false><<<NB, 512, SM_CG>>>(W_con1, b_con1, W_ih, b_ih,
                                        W_lin1, b_lin1, nullptr);
    k_zero<<<1024, 256>>>();
    k_prop<<<PROP_BLOCKS, 256>>>(1, ei, ew, eir, ewr);
    k_congru<true><<<NB, 512, SM_CG>>>(W_con2, b_con2, W_ih, b_ih,
                                       W_out, b_out, out);
}

// round 4
// speedup vs baseline: 6.5176x; 1.0792x over previous
#include <cuda_runtime.h>
#include <cuda_fp16.h>
#include <math.h>
#include <stdint.h>

#define NN 100000
#define FF 128
#define HH 64
#define CC 16
#define EE 1000000
#define KP128 132
#define KP64 68

// ---------------- scratch ----------------------------------------------------
__device__ __align__(16) float  g_h0[NN * HH];
__device__ __align__(16) __half g_h0h[NN * HH];
__device__ __align__(16) __half g_xmidh[NN * HH];
__device__ __align__(16) float  g_ghh[NN * 192];
__device__ __align__(16) float  g_x1[NN * HH];
__device__ __align__(16) float  g_x2[NN * HH];

// ---------------- tf32 mma helpers ------------------------------------------
__device__ __forceinline__ uint32_t f2tf(float f) {
    uint32_t u;
    asm("cvt.rna.tf32.f32 %0, %1;" : "=r"(u) : "f"(f));
    return u;
}
__device__ __forceinline__ void mma8(float4& d, uint32_t a0, uint32_t a1,
                                     uint32_t a2, uint32_t a3,
                                     uint32_t b0, uint32_t b1) {
    asm volatile(
        "mma.sync.aligned.m16n8k8.row.col.f32.tf32.tf32.f32 "
        "{%0,%1,%2,%3},{%4,%5,%6,%7},{%8,%9},{%0,%1,%2,%3};"
        : "+f"(d.x), "+f"(d.y), "+f"(d.z), "+f"(d.w)
        : "r"(a0), "r"(a1), "r"(a2), "r"(a3), "r"(b0), "r"(b1));
}
__device__ __forceinline__ float sigf(float x) {
    return 1.f / (1.f + __expf(-x));
}

// ---------------- zero the two scatter buffers -------------------------------
__global__ void k_zero() {
    const int tot = NN * HH / 4;
    float4 z = make_float4(0.f, 0.f, 0.f, 0.f);
    for (int i = blockIdx.x * blockDim.x + threadIdx.x; i < tot;
         i += gridDim.x * blockDim.x) {
        reinterpret_cast<float4*>(g_x1)[i] = z;
        reinterpret_cast<float4*>(g_x2)[i] = z;
    }
}

// ---------------- fused k_fg: h0 = x@Wf^T+bf ; ghh = h0@Whh^T+bhh ------------
// 128 nodes/block, 512 threads, tf32 mma. h0 tile stays in smem between GEMMs.
#define FG_A    0                          // 128x132 x (tf32)
#define FG_WF   (FG_A + 128 * KP128)       // 64x132
#define FG_WHH  (FG_WF + 64 * KP128)       // 192x68
#define FG_G    (FG_WHH + 192 * KP64)      // 128x68 h0 (tf32)
#define FG_WORDS (FG_G + 128 * KP64)

__global__ __launch_bounds__(512, 1) void k_fg(const float* __restrict__ x,
                                               const float* __restrict__ Wf,
                                               const float* __restrict__ bf,
                                               const float* __restrict__ Whh,
                                               const float* __restrict__ bhh) {
    extern __shared__ uint32_t sm[];
    uint32_t* sA   = sm + FG_A;
    uint32_t* sWf  = sm + FG_WF;
    uint32_t* sWhh = sm + FG_WHH;
    uint32_t* sG   = sm + FG_G;
    __shared__ float sbf[64];
    __shared__ float sbhh[192];
    int t = threadIdx.x;
    int base = blockIdx.x * 128;

    for (int i = t; i < 128 * 32; i += 512) {
        int node = i >> 5, q = i & 31;
        float4 v = make_float4(0.f, 0.f, 0.f, 0.f);
        if (base + node < NN)
            v = *(const float4*)(x + (base + node) * FF + q * 4);
        uint32_t* d = sA + node * KP128 + q * 4;
        d[0] = f2tf(v.x); d[1] = f2tf(v.y); d[2] = f2tf(v.z); d[3] = f2tf(v.w);
    }
    for (int i = t; i < 64 * 32; i += 512) {
        int o = i >> 5, q = i & 31;
        float4 v = *(const float4*)(Wf + o * FF + q * 4);
        uint32_t* d = sWf + o * KP128 + q * 4;
        d[0] = f2tf(v.x); d[1] = f2tf(v.y); d[2] = f2tf(v.z); d[3] = f2tf(v.w);
    }
    for (int i = t; i < 192 * 16; i += 512) {
        int o = i >> 4, q = i & 15;
        float4 v = *(const float4*)(Whh + o * HH + q * 4);
        uint32_t* d = sWhh + o * KP64 + q * 4;
        d[0] = f2tf(v.x); d[1] = f2tf(v.y); d[2] = f2tf(v.z); d[3] = f2tf(v.w);
    }
    if (t < 64) sbf[t] = bf[t];
    if (t >= 256 && t < 448) sbhh[t - 256] = bhh[t - 256];
    __syncthreads();

    int w = t >> 5, lane = t & 31, g = lane >> 2, tig = lane & 3;
    int r0 = (w & 7) * 16;

    // GEMM1: h0 = x @ Wf^T
    {
        int cb = (w >> 3) * 32;
        float4 acc[4] = {};
#pragma unroll 4
        for (int ks = 0; ks < 16; ks++) {
            int ko = ks * 8;
            uint32_t a0 = sA[(r0 + g) * KP128 + ko + tig];
            uint32_t a1 = sA[(r0 + g + 8) * KP128 + ko + tig];
            uint32_t a2 = sA[(r0 + g) * KP128 + ko + tig + 4];
            uint32_t a3 = sA[(r0 + g + 8) * KP128 + ko + tig + 4];
#pragma unroll
            for (int nt = 0; nt < 4; nt++) {
                int o = cb + nt * 8 + g;
                mma8(acc[nt], a0, a1, a2, a3,
                     sWf[o * KP128 + ko + tig], sWf[o * KP128 + ko + tig + 4]);
            }
        }
#pragma unroll
        for (int nt = 0; nt < 4; nt++) {
            int c = cb + nt * 8 + tig * 2;
            int n1 = base + r0 + g, n2 = n1 + 8;
            float v0 = acc[nt].x + sbf[c], v1 = acc[nt].y + sbf[c + 1];
            float v2 = acc[nt].z + sbf[c], v3 = acc[nt].w + sbf[c + 1];
            if (n1 < NN) {
                *(float2*)(g_h0 + n1 * HH + c) = make_float2(v0, v1);
                *(__half2*)(g_h0h + n1 * HH + c) = __floats2half2_rn(v0, v1);
            }
            if (n2 < NN) {
                *(float2*)(g_h0 + n2 * HH + c) = make_float2(v2, v3);
                *(__half2*)(g_h0h + n2 * HH + c) = __floats2half2_rn(v2, v3);
            }
            sG[(r0 + g) * KP64 + c]         = f2tf(v0);
            sG[(r0 + g) * KP64 + c + 1]     = f2tf(v1);
            sG[(r0 + g + 8) * KP64 + c]     = f2tf(v2);
            sG[(r0 + g + 8) * KP64 + c + 1] = f2tf(v3);
        }
    }
    __syncthreads();

    // GEMM2: ghh = h0 @ Whh^T (192 outputs, 12 n-tiles/warp)
    {
        int cb = (w >> 3) * 96;
        float4 acc[12] = {};
        for (int ks = 0; ks < 8; ks++) {
            int ko = ks * 8;
            uint32_t a0 = sG[(r0 + g) * KP64 + ko + tig];
            uint32_t a1 = sG[(r0 + g + 8) * KP64 + ko + tig];
            uint32_t a2 = sG[(r0 + g) * KP64 + ko + tig + 4];
            uint32_t a3 = sG[(r0 + g + 8) * KP64 + ko + tig + 4];
#pragma unroll
            for (int nt = 0; nt < 12; nt++) {
                int o = cb + nt * 8 + g;
                mma8(acc[nt], a0, a1, a2, a3,
                     sWhh[o * KP64 + ko + tig], sWhh[o * KP64 + ko + tig + 4]);
            }
        }
#pragma unroll
        for (int nt = 0; nt < 12; nt++) {
            int c = cb + nt * 8 + tig * 2;
            int n1 = base + r0 + g, n2 = n1 + 8;
            if (n1 < NN)
                *(float2*)(g_ghh + n1 * 192 + c) =
                    make_float2(acc[nt].x + sbhh[c], acc[nt].y + sbhh[c + 1]);
            if (n2 < NN)
                *(float2*)(g_ghh + n2 * 192 + c) =
                    make_float2(acc[nt].z + sbhh[c], acc[nt].w + sbhh[c + 1]);
        }
    }
}

// ---------------- edge propagation: fp16 gather, fp32 RED, 2 edges/thread ----
__global__ __launch_bounds__(256) void k_prop(int use_mid,
                                              const int* __restrict__ ei1,
                                              const float* __restrict__ ew1,
                                              const int* __restrict__ ei2,
                                              const float* __restrict__ ew2) {
    const __half* xin = use_mid ? g_xmidh : g_h0h;
    int group = blockIdx.x * 16 + (threadIdx.x >> 4);
    int l16 = threadIdx.x & 15;
    int slot0 = group * 2;  // even; pair never straddles EE

    const int* ei;
    const float* ew;
    float* out;
    int e0;
    if (slot0 < EE) { e0 = slot0;      ei = ei1; ew = ew1; out = g_x1; }
    else            { e0 = slot0 - EE; ei = ei2; ew = ew2; out = g_x2; }

    int s0 = __ldg(ei + e0),      s1 = __ldg(ei + e0 + 1);
    int d0 = __ldg(ei + EE + e0), d1 = __ldg(ei + EE + e0 + 1);
    float w0 = __ldg(ew + e0),    w1 = __ldg(ew + e0 + 1);

    const __half2* p0 = (const __half2*)(xin + s0 * HH + l16 * 4);
    const __half2* p1 = (const __half2*)(xin + s1 * HH + l16 * 4);
    __half2 a0 = p0[0], a1 = p0[1];
    __half2 b0 = p1[0], b1 = p1[1];

    float2 f0 = __half22float2(a0), f1 = __half22float2(a1);
    float2 g0 = __half22float2(b0), g1 = __half22float2(b1);

    float* q0 = out + d0 * HH + l16 * 4;
    float* q1 = out + d1 * HH + l16 * 4;
    asm volatile("red.global.add.v4.f32 [%0], {%1, %2, %3, %4};"
                 :: "l"(q0), "f"(f0.x * w0), "f"(f0.y * w0),
                    "f"(f1.x * w0), "f"(f1.y * w0) : "memory");
    asm volatile("red.global.add.v4.f32 [%0], {%1, %2, %3, %4};"
                 :: "l"(q1), "f"(g0.x * w1), "f"(g0.y * w1),
                    "f"(g1.x * w1), "f"(g1.y * w1) : "memory");
}

// ---------------- fused concat-linear + GRU + (lin | out+logsoftmax) --------
#define O_A    0
#define O_WC   (O_A + 128 * KP128)
#define O_WIH  (O_WC + 64 * KP128)
#define O_WL   (O_WIH + 192 * KP64)
#define O_G    (O_WL + 64 * KP64)
#define O_BC   (O_G + 128 * KP64)
#define O_BIH  (O_BC + 64)
#define O_BL   (O_BIH + 192)
#define CG_WORDS (O_BL + 64)

template <bool FINAL>
__global__ __launch_bounds__(512, 1) void k_congru(
    const float* __restrict__ Wc,  const float* __restrict__ bc,
    const float* __restrict__ Wih, const float* __restrict__ bih,
    const float* __restrict__ Wl,  const float* __restrict__ bl,
    float* __restrict__ dout) {
    extern __shared__ uint32_t sm[];
    uint32_t* sA   = sm + O_A;
    uint32_t* sWc  = sm + O_WC;
    uint32_t* sWih = sm + O_WIH;
    uint32_t* sWl  = sm + O_WL;
    uint32_t* sG   = sm + O_G;
    float* sbc  = (float*)(sm + O_BC);
    float* sbih = (float*)(sm + O_BIH);
    float* sbl  = (float*)(sm + O_BL);
    const int OC = FINAL ? CC : HH;

    int t = threadIdx.x;
    int base = blockIdx.x * 128;

    for (int i = t; i < 128 * 16; i += 512) {
        int node = i >> 4, q = i & 15;
        int n = base + node;
        float4 v1 = make_float4(0.f, 0.f, 0.f, 0.f), v2 = v1;
        if (n < NN) {
            v1 = *(const float4*)(g_x1 + n * HH + q * 4);
            v2 = *(const float4*)(g_x2 + n * HH + q * 4);
        }
        uint32_t* d1 = sA + node * KP128 + q * 4;
        uint32_t* d2 = d1 + 64;
        d1[0] = f2tf(v1.x); d1[1] = f2tf(v1.y); d1[2] = f2tf(v1.z); d1[3] = f2tf(v1.w);
        d2[0] = f2tf(v2.x); d2[1] = f2tf(v2.y); d2[2] = f2tf(v2.z); d2[3] = f2tf(v2.w);
    }
    for (int i = t; i < 64 * 32; i += 512) {
        int o = i >> 5, q = i & 31;
        float4 v = *(const float4*)(Wc + o * FF + q * 4);
        uint32_t* d = sWc + o * KP128 + q * 4;
        d[0] = f2tf(v.x); d[1] = f2tf(v.y); d[2] = f2tf(v.z); d[3] = f2tf(v.w);
    }
    for (int i = t; i < 192 * 16; i += 512) {
        int o = i >> 4, q = i & 15;
        float4 v = *(const float4*)(Wih + o * HH + q * 4);
        uint32_t* d = sWih + o * KP64 + q * 4;
        d[0] = f2tf(v.x); d[1] = f2tf(v.y); d[2] = f2tf(v.z); d[3] = f2tf(v.w);
    }
    for (int i = t; i < OC * 16; i += 512) {
        int o = i >> 4, q = i & 15;
        float4 v = *(const float4*)(Wl + o * HH + q * 4);
        uint32_t* d = sWl + o * KP64 + q * 4;
        d[0] = f2tf(v.x); d[1] = f2tf(v.y); d[2] = f2tf(v.z); d[3] = f2tf(v.w);
    }
    if (t < 64)  sbc[t]  = bc[t];
    if (t < 192) sbih[t] = bih[t];
    if (t < OC)  sbl[t]  = bl[t];
    __syncthreads();

    int w = t >> 5, lane = t & 31, g = lane >> 2, tig = lane & 3;
    int r0 = (w & 7) * 16, cb = (w >> 3) * 32;

    // phase 1: gg = [x1|x2] @ Wc^T + bc
    {
        float4 acc[4] = {};
#pragma unroll 4
        for (int ks = 0; ks < 16; ks++) {
            int ko = ks * 8;
            uint32_t a0 = sA[(r0 + g) * KP128 + ko + tig];
            uint32_t a1 = sA[(r0 + g + 8) * KP128 + ko + tig];
            uint32_t a2 = sA[(r0 + g) * KP128 + ko + tig + 4];
            uint32_t a3 = sA[(r0 + g + 8) * KP128 + ko + tig + 4];
#pragma unroll
            for (int nt = 0; nt < 4; nt++) {
                int o = cb + nt * 8 + g;
                mma8(acc[nt], a0, a1, a2, a3,
                     sWc[o * KP128 + ko + tig], sWc[o * KP128 + ko + tig + 4]);
            }
        }
        __syncthreads();
#pragma unroll
        for (int nt = 0; nt < 4; nt++) {
            int c = cb + nt * 8 + tig * 2;
            sG[(r0 + g) * KP64 + c]         = f2tf(acc[nt].x + sbc[c]);
            sG[(r0 + g) * KP64 + c + 1]     = f2tf(acc[nt].y + sbc[c + 1]);
            sG[(r0 + g + 8) * KP64 + c]     = f2tf(acc[nt].z + sbc[c]);
            sG[(r0 + g + 8) * KP64 + c + 1] = f2tf(acc[nt].w + sbc[c + 1]);
        }
    }
    __syncthreads();

    // phase 2: gi = gg @ Wih^T
    float4 d2[3][4];
#pragma unroll
    for (int gt = 0; gt < 3; gt++)
#pragma unroll
        for (int nt = 0; nt < 4; nt++) d2[gt][nt] = make_float4(0.f, 0.f, 0.f, 0.f);
    for (int ks = 0; ks < 8; ks++) {
        int ko = ks * 8;
        uint32_t a0 = sG[(r0 + g) * KP64 + ko + tig];
        uint32_t a1 = sG[(r0 + g + 8) * KP64 + ko + tig];
        uint32_t a2 = sG[(r0 + g) * KP64 + ko + tig + 4];
        uint32_t a3 = sG[(r0 + g + 8) * KP64 + ko + tig + 4];
#pragma unroll
        for (int gt = 0; gt < 3; gt++)
#pragma unroll
            for (int nt = 0; nt < 4; nt++) {
                int o = gt * 64 + cb + nt * 8 + g;
                mma8(d2[gt][nt], a0, a1, a2, a3,
                     sWih[o * KP64 + ko + tig], sWih[o * KP64 + ko + tig + 4]);
            }
    }

    // phase 3: GRU elementwise
    float hn[4][4];
#pragma unroll
    for (int nt = 0; nt < 4; nt++) {
        int c = cb + nt * 8 + tig * 2;
#pragma unroll
        for (int half = 0; half < 2; half++) {
            int node = base + r0 + g + half * 8;
            float vr0 = half ? d2[0][nt].z : d2[0][nt].x;
            float vr1 = half ? d2[0][nt].w : d2[0][nt].y;
            float vz0 = half ? d2[1][nt].z : d2[1][nt].x;
            float vz1 = half ? d2[1][nt].w : d2[1][nt].y;
            float vn0 = half ? d2[2][nt].z : d2[2][nt].x;
            float vn1 = half ? d2[2][nt].w : d2[2][nt].y;
            float o0 = 0.f, o1 = 0.f;
            if (node < NN) {
                float2 gr = *(const float2*)(g_ghh + node * 192 + c);
                float2 gz = *(const float2*)(g_ghh + node * 192 + 64 + c);
                float2 gn = *(const float2*)(g_ghh + node * 192 + 128 + c);
                float2 h  = *(const float2*)(g_h0 + node * HH + c);
                float r = sigf(vr0 + sbih[c] + gr.x);
                float z = sigf(vz0 + sbih[64 + c] + gz.x);
                float n = tanhf(vn0 + sbih[128 + c] + r * gn.x);
                o0 = (1.f - z) * n + z * h.x;
                r = sigf(vr1 + sbih[c + 1] + gr.y);
                z = sigf(vz1 + sbih[64 + c + 1] + gz.y);
                n = tanhf(vn1 + sbih[128 + c + 1] + r * gn.y);
                o1 = (1.f - z) * n + z * h.y;
            }
            hn[nt][half * 2] = o0;
            hn[nt][half * 2 + 1] = o1;
        }
    }
    __syncthreads();
#pragma unroll
    for (int nt = 0; nt < 4; nt++) {
        int c = cb + nt * 8 + tig * 2;
        sG[(r0 + g) * KP64 + c]         = f2tf(hn[nt][0]);
        sG[(r0 + g) * KP64 + c + 1]     = f2tf(hn[nt][1]);
        sG[(r0 + g + 8) * KP64 + c]     = f2tf(hn[nt][2]);
        sG[(r0 + g + 8) * KP64 + c + 1] = f2tf(hn[nt][3]);
    }
    __syncthreads();

    // phase 4: output GEMM
    if (!FINAL) {
        float4 acc[4] = {};
        for (int ks = 0; ks < 8; ks++) {
            int ko = ks * 8;
            uint32_t a0 = sG[(r0 + g) * KP64 + ko + tig];
            uint32_t a1 = sG[(r0 + g + 8) * KP64 + ko + tig];
            uint32_t a2 = sG[(r0 + g) * KP64 + ko + tig + 4];
            uint32_t a3 = sG[(r0 + g + 8) * KP64 + ko + tig + 4];
#pragma unroll
            for (int nt = 0; nt < 4; nt++) {
                int o = cb + nt * 8 + g;
                mma8(acc[nt], a0, a1, a2, a3,
                     sWl[o * KP64 + ko + tig], sWl[o * KP64 + ko + tig + 4]);
            }
        }
#pragma unroll
        for (int nt = 0; nt < 4; nt++) {
            int c = cb + nt * 8 + tig * 2;
            int n1 = base + r0 + g, n2 = n1 + 8;
            if (n1 < NN)
                *(__half2*)(g_xmidh + n1 * HH + c) =
                    __floats2half2_rn(acc[nt].x + sbl[c], acc[nt].y + sbl[c + 1]);
            if (n2 < NN)
                *(__half2*)(g_xmidh + n2 * HH + c) =
                    __floats2half2_rn(acc[nt].z + sbl[c], acc[nt].w + sbl[c + 1]);
        }
    } else {
        float4 acc = make_float4(0.f, 0.f, 0.f, 0.f);
        int c0f = (w >> 3) * 8;
        for (int ks = 0; ks < 8; ks++) {
            int ko = ks * 8;
            uint32_t a0 = sG[(r0 + g) * KP64 + ko + tig];
            uint32_t a1 = sG[(r0 + g + 8) * KP64 + ko + tig];
            uint32_t a2 = sG[(r0 + g) * KP64 + ko + tig + 4];
            uint32_t a3 = sG[(r0 + g + 8) * KP64 + ko + tig + 4];
            int o = c0f + g;
            mma8(acc, a0, a1, a2, a3,
                 sWl[o * KP64 + ko + tig], sWl[o * KP64 + ko + tig + 4]);
        }
        float* ly = (float*)sWc;
        int c = c0f + tig * 2;
        ly[(r0 + g) * 17 + c]         = acc.x + sbl[c];
        ly[(r0 + g) * 17 + c + 1]     = acc.y + sbl[c + 1];
        ly[(r0 + g + 8) * 17 + c]     = acc.z + sbl[c];
        ly[(r0 + g + 8) * 17 + c + 1] = acc.w + sbl[c + 1];
        __syncthreads();
        if (t < 128) {
            int node = base + t;
            if (node < NN) {
                float m = -1e30f;
#pragma unroll
                for (int cc = 0; cc < 16; cc++) m = fmaxf(m, ly[t * 17 + cc]);
                float s = 0.f;
#pragma unroll
                for (int cc = 0; cc < 16; cc++) s += expf(ly[t * 17 + cc] - m);
                float l = m + logf(s);
#pragma unroll
                for (int cc = 0; cc < 16; cc++)
                    dout[node * CC + cc] = ly[t * 17 + cc] - l;
            }
        }
    }
}

// ---------------- launch -----------------------------------------------------
extern "C" void kernel_launch(void* const* d_in, const int* in_sizes, int n_in,
                              void* d_out, int out_size) {
    const float* x       = (const float*)d_in[0];
    const int*   ei      = (const int*)  d_in[1];
    const float* ew      = (const float*)d_in[2];
    const int*   eir     = (const int*)  d_in[3];
    const float* ewr     = (const float*)d_in[4];
    const float* W_first = (const float*)d_in[5];
    const float* b_first = (const float*)d_in[6];
    const float* W_con1  = (const float*)d_in[7];
    const float* b_con1  = (const float*)d_in[8];
    const float* W_con2  = (const float*)d_in[9];
    const float* b_con2  = (const float*)d_in[10];
    const float* W_lin1  = (const float*)d_in[11];
    const float* b_lin1  = (const float*)d_in[12];
    const float* W_out   = (const float*)d_in[13];
    const float* b_out   = (const float*)d_in[14];
    const float* W_ih    = (const float*)d_in[15];
    const float* W_hh    = (const float*)d_in[16];
    const float* b_ih    = (const float*)d_in[17];
    const float* b_hh    = (const float*)d_in[18];
    float* out = (float*)d_out;

    const int SM_FG = FG_WORDS * 4;
    const int SM_CG = CG_WORDS * 4;

    cudaFuncSetAttribute(k_fg, cudaFuncAttributeMaxDynamicSharedMemorySize, SM_FG);
    cudaFuncSetAttribute(k_congru<false>,
                         cudaFuncAttributeMaxDynamicSharedMemorySize, SM_CG);
    cudaFuncSetAttribute(k_congru<true>,
                         cudaFuncAttributeMaxDynamicSharedMemorySize, SM_CG);

    const int NB = (NN + 127) / 128;          // 782
    const int PROP_BLOCKS = (2 * EE) / 32;    // 2 edges/16-lane group

    k_zero<<<1024, 256>>>();
    k_fg<<<NB, 512, SM_FG>>>(x, W_first, b_first, W_hh, b_hh);
    k_prop<<<PROP_BLOCKS, 256>>>(0, ei, ew, eir, ewr);
    k_congru<false><<<NB, 512, SM_CG>>>(W_con1, b_con1, W_ih, b_ih,
                                        W_lin1, b_lin1, nullptr);
    k_zero<<<1024, 256>>>();
    k_prop<<<PROP_BLOCKS, 256>>>(1, ei, ew, eir, ewr);
    k_congru<true><<<NB, 512, SM_CG>>>(W_con2, b_con2, W_ih, b_ih,
                                       W_out, b_out, out);
}

// round 5
// speedup vs baseline: 7.4066x; 1.1364x over previous
#include <cuda_runtime.h>
#include <cuda_fp16.h>
#include <math.h>
#include <stdint.h>

#define NN 100000
#define FF 128
#define HH 64
#define CC 16
#define EE 1000000
#define KP128 132
#define KP64 68
#define NB 782   // ceil(NN/128)

// ---------------- scratch ----------------------------------------------------
__device__ __align__(16) float  g_h0[NN * HH];
__device__ __align__(16) __half g_h0h[NN * HH];
__device__ __align__(16) __half g_xmidh[NN * HH];
__device__ __align__(16) __half g_ghhh[NN * 192];
__device__ __align__(16) float  g_x1[NN * HH];
__device__ __align__(16) float  g_x2[NN * HH];

// ---------------- tf32 mma helpers ------------------------------------------
__device__ __forceinline__ uint32_t f2tf(float f) {
    uint32_t u;
    asm("cvt.rna.tf32.f32 %0, %1;" : "=r"(u) : "f"(f));
    return u;
}
__device__ __forceinline__ void mma8(float4& d, uint32_t a0, uint32_t a1,
                                     uint32_t a2, uint32_t a3,
                                     uint32_t b0, uint32_t b1) {
    asm volatile(
        "mma.sync.aligned.m16n8k8.row.col.f32.tf32.tf32.f32 "
        "{%0,%1,%2,%3},{%4,%5,%6,%7},{%8,%9},{%0,%1,%2,%3};"
        : "+f"(d.x), "+f"(d.y), "+f"(d.z), "+f"(d.w)
        : "r"(a0), "r"(a1), "r"(a2), "r"(a3), "r"(b0), "r"(b1));
}
__device__ __forceinline__ float sigf(float x) {
    return 1.f / (1.f + __expf(-x));
}

// ---------------- zero the two scatter buffers -------------------------------
__global__ void k_zero() {
    const int tot = NN * HH / 4;
    float4 z = make_float4(0.f, 0.f, 0.f, 0.f);
    for (int i = blockIdx.x * blockDim.x + threadIdx.x; i < tot;
         i += gridDim.x * blockDim.x) {
        reinterpret_cast<float4*>(g_x1)[i] = z;
        reinterpret_cast<float4*>(g_x2)[i] = z;
    }
}

// ---------------- persistent k_fg: h0 = x@Wf^T+bf ; ghh = h0@Whh^T+bhh -------
#define FG_A    0                          // 128x132
#define FG_WF   (FG_A + 128 * KP128)       // 64x132
#define FG_WHH  (FG_WF + 64 * KP128)       // 192x68
#define FG_G    (FG_WHH + 192 * KP64)      // 128x68
#define FG_WORDS (FG_G + 128 * KP64)

__global__ __launch_bounds__(512, 1) void k_fg(const float* __restrict__ x,
                                               const float* __restrict__ Wf,
                                               const float* __restrict__ bf,
                                               const float* __restrict__ Whh,
                                               const float* __restrict__ bhh) {
    extern __shared__ uint32_t sm[];
    uint32_t* sA   = sm + FG_A;
    uint32_t* sWf  = sm + FG_WF;
    uint32_t* sWhh = sm + FG_WHH;
    uint32_t* sG   = sm + FG_G;
    __shared__ float sbf[64];
    __shared__ float sbhh[192];
    int t = threadIdx.x;

    // stage weights ONCE
    for (int i = t; i < 64 * 32; i += 512) {
        int o = i >> 5, q = i & 31;
        float4 v = *(const float4*)(Wf + o * FF + q * 4);
        uint32_t* d = sWf + o * KP128 + q * 4;
        d[0] = f2tf(v.x); d[1] = f2tf(v.y); d[2] = f2tf(v.z); d[3] = f2tf(v.w);
    }
    for (int i = t; i < 192 * 16; i += 512) {
        int o = i >> 4, q = i & 15;
        float4 v = *(const float4*)(Whh + o * HH + q * 4);
        uint32_t* d = sWhh + o * KP64 + q * 4;
        d[0] = f2tf(v.x); d[1] = f2tf(v.y); d[2] = f2tf(v.z); d[3] = f2tf(v.w);
    }
    if (t < 64) sbf[t] = bf[t];
    if (t >= 256 && t < 448) sbhh[t - 256] = bhh[t - 256];
    __syncthreads();

    int w = t >> 5, lane = t & 31, g = lane >> 2, tig = lane & 3;
    int r0 = (w & 7) * 16;

    for (int tile = blockIdx.x; tile < NB; tile += gridDim.x) {
        int base = tile * 128;
        for (int i = t; i < 128 * 32; i += 512) {
            int node = i >> 5, q = i & 31;
            float4 v = make_float4(0.f, 0.f, 0.f, 0.f);
            if (base + node < NN)
                v = *(const float4*)(x + (base + node) * FF + q * 4);
            uint32_t* d = sA + node * KP128 + q * 4;
            d[0] = f2tf(v.x); d[1] = f2tf(v.y); d[2] = f2tf(v.z); d[3] = f2tf(v.w);
        }
        __syncthreads();

        // GEMM1: h0 = x @ Wf^T
        {
            int cb = (w >> 3) * 32;
            float4 acc[4] = {};
#pragma unroll 4
            for (int ks = 0; ks < 16; ks++) {
                int ko = ks * 8;
                uint32_t a0 = sA[(r0 + g) * KP128 + ko + tig];
                uint32_t a1 = sA[(r0 + g + 8) * KP128 + ko + tig];
                uint32_t a2 = sA[(r0 + g) * KP128 + ko + tig + 4];
                uint32_t a3 = sA[(r0 + g + 8) * KP128 + ko + tig + 4];
#pragma unroll
                for (int nt = 0; nt < 4; nt++) {
                    int o = cb + nt * 8 + g;
                    mma8(acc[nt], a0, a1, a2, a3,
                         sWf[o * KP128 + ko + tig], sWf[o * KP128 + ko + tig + 4]);
                }
            }
#pragma unroll
            for (int nt = 0; nt < 4; nt++) {
                int c = cb + nt * 8 + tig * 2;
                int n1 = base + r0 + g, n2 = n1 + 8;
                float v0 = acc[nt].x + sbf[c], v1 = acc[nt].y + sbf[c + 1];
                float v2 = acc[nt].z + sbf[c], v3 = acc[nt].w + sbf[c + 1];
                if (n1 < NN) {
                    *(float2*)(g_h0 + n1 * HH + c) = make_float2(v0, v1);
                    *(__half2*)(g_h0h + n1 * HH + c) = __floats2half2_rn(v0, v1);
                }
                if (n2 < NN) {
                    *(float2*)(g_h0 + n2 * HH + c) = make_float2(v2, v3);
                    *(__half2*)(g_h0h + n2 * HH + c) = __floats2half2_rn(v2, v3);
                }
                sG[(r0 + g) * KP64 + c]         = f2tf(v0);
                sG[(r0 + g) * KP64 + c + 1]     = f2tf(v1);
                sG[(r0 + g + 8) * KP64 + c]     = f2tf(v2);
                sG[(r0 + g + 8) * KP64 + c + 1] = f2tf(v3);
            }
        }
        __syncthreads();

        // GEMM2: ghh = h0 @ Whh^T
        {
            int cb = (w >> 3) * 96;
            float4 acc[12] = {};
            for (int ks = 0; ks < 8; ks++) {
                int ko = ks * 8;
                uint32_t a0 = sG[(r0 + g) * KP64 + ko + tig];
                uint32_t a1 = sG[(r0 + g + 8) * KP64 + ko + tig];
                uint32_t a2 = sG[(r0 + g) * KP64 + ko + tig + 4];
                uint32_t a3 = sG[(r0 + g + 8) * KP64 + ko + tig + 4];
#pragma unroll
                for (int nt = 0; nt < 12; nt++) {
                    int o = cb + nt * 8 + g;
                    mma8(acc[nt], a0, a1, a2, a3,
                         sWhh[o * KP64 + ko + tig], sWhh[o * KP64 + ko + tig + 4]);
                }
            }
#pragma unroll
            for (int nt = 0; nt < 12; nt++) {
                int c = cb + nt * 8 + tig * 2;
                int n1 = base + r0 + g, n2 = n1 + 8;
                if (n1 < NN)
                    *(__half2*)(g_ghhh + n1 * 192 + c) =
                        __floats2half2_rn(acc[nt].x + sbhh[c], acc[nt].y + sbhh[c + 1]);
                if (n2 < NN)
                    *(__half2*)(g_ghhh + n2 * 192 + c) =
                        __floats2half2_rn(acc[nt].z + sbhh[c], acc[nt].w + sbhh[c + 1]);
            }
        }
        __syncthreads();
    }
}

// ---------------- edge propagation: fp16 gather, fp32 RED, 2 edges/thread ----
__global__ __launch_bounds__(256) void k_prop(int use_mid,
                                              const int* __restrict__ ei1,
                                              const float* __restrict__ ew1,
                                              const int* __restrict__ ei2,
                                              const float* __restrict__ ew2) {
    const __half* xin = use_mid ? g_xmidh : g_h0h;
    int group = blockIdx.x * 16 + (threadIdx.x >> 4);
    int l16 = threadIdx.x & 15;
    int slot0 = group * 2;

    const int* ei;
    const float* ew;
    float* out;
    int e0;
    if (slot0 < EE) { e0 = slot0;      ei = ei1; ew = ew1; out = g_x1; }
    else            { e0 = slot0 - EE; ei = ei2; ew = ew2; out = g_x2; }

    int s0 = __ldg(ei + e0),      s1 = __ldg(ei + e0 + 1);
    int d0 = __ldg(ei + EE + e0), d1 = __ldg(ei + EE + e0 + 1);
    float w0 = __ldg(ew + e0),    w1 = __ldg(ew + e0 + 1);

    const __half2* p0 = (const __half2*)(xin + s0 * HH + l16 * 4);
    const __half2* p1 = (const __half2*)(xin + s1 * HH + l16 * 4);
    __half2 a0 = p0[0], a1 = p0[1];
    __half2 b0 = p1[0], b1 = p1[1];

    float2 f0 = __half22float2(a0), f1 = __half22float2(a1);
    float2 g0 = __half22float2(b0), g1 = __half22float2(b1);

    float* q0 = out + d0 * HH + l16 * 4;
    float* q1 = out + d1 * HH + l16 * 4;
    asm volatile("red.global.add.v4.f32 [%0], {%1, %2, %3, %4};"
                 :: "l"(q0), "f"(f0.x * w0), "f"(f0.y * w0),
                    "f"(f1.x * w0), "f"(f1.y * w0) : "memory");
    asm volatile("red.global.add.v4.f32 [%0], {%1, %2, %3, %4};"
                 :: "l"(q1), "f"(g0.x * w1), "f"(g0.y * w1),
                    "f"(g1.x * w1), "f"(g1.y * w1) : "memory");
}

// ---------------- persistent fused concat-linear + GRU + out ----------------
#define O_A    0
#define O_WC   (O_A + 128 * KP128)
#define O_WIH  (O_WC + 64 * KP128)
#define O_WL   (O_WIH + 192 * KP64)
#define O_G    (O_WL + 64 * KP64)
#define O_BC   (O_G + 128 * KP64)
#define O_BIH  (O_BC + 64)
#define O_BL   (O_BIH + 192)
#define O_LY   (O_BL + 64)
#define CG_WORDS (O_LY + 128 * 17)

template <bool FINAL>
__global__ __launch_bounds__(512, 1) void k_congru(
    const float* __restrict__ Wc,  const float* __restrict__ bc,
    const float* __restrict__ Wih, const float* __restrict__ bih,
    const float* __restrict__ Wl,  const float* __restrict__ bl,
    float* __restrict__ dout) {
    extern __shared__ uint32_t sm[];
    uint32_t* sA   = sm + O_A;
    uint32_t* sWc  = sm + O_WC;
    uint32_t* sWih = sm + O_WIH;
    uint32_t* sWl  = sm + O_WL;
    uint32_t* sG   = sm + O_G;
    float* sbc  = (float*)(sm + O_BC);
    float* sbih = (float*)(sm + O_BIH);
    float* sbl  = (float*)(sm + O_BL);
    float* sLY  = (float*)(sm + O_LY);
    const int OC = FINAL ? CC : HH;

    int t = threadIdx.x;

    // stage weights ONCE
    for (int i = t; i < 64 * 32; i += 512) {
        int o = i >> 5, q = i & 31;
        float4 v = *(const float4*)(Wc + o * FF + q * 4);
        uint32_t* d = sWc + o * KP128 + q * 4;
        d[0] = f2tf(v.x); d[1] = f2tf(v.y); d[2] = f2tf(v.z); d[3] = f2tf(v.w);
    }
    for (int i = t; i < 192 * 16; i += 512) {
        int o = i >> 4, q = i & 15;
        float4 v = *(const float4*)(Wih + o * HH + q * 4);
        uint32_t* d = sWih + o * KP64 + q * 4;
        d[0] = f2tf(v.x); d[1] = f2tf(v.y); d[2] = f2tf(v.z); d[3] = f2tf(v.w);
    }
    for (int i = t; i < OC * 16; i += 512) {
        int o = i >> 4, q = i & 15;
        float4 v = *(const float4*)(Wl + o * HH + q * 4);
        uint32_t* d = sWl + o * KP64 + q * 4;
        d[0] = f2tf(v.x); d[1] = f2tf(v.y); d[2] = f2tf(v.z); d[3] = f2tf(v.w);
    }
    if (t < 64)  sbc[t]  = bc[t];
    if (t < 192) sbih[t] = bih[t];
    if (t < OC)  sbl[t]  = bl[t];
    __syncthreads();

    int w = t >> 5, lane = t & 31, g = lane >> 2, tig = lane & 3;
    int r0 = (w & 7) * 16, cb = (w >> 3) * 32;

    for (int tile = blockIdx.x; tile < NB; tile += gridDim.x) {
        int base = tile * 128;
        for (int i = t; i < 128 * 16; i += 512) {
            int node = i >> 4, q = i & 15;
            int n = base + node;
            float4 v1 = make_float4(0.f, 0.f, 0.f, 0.f), v2 = v1;
            if (n < NN) {
                v1 = *(const float4*)(g_x1 + n * HH + q * 4);
                v2 = *(const float4*)(g_x2 + n * HH + q * 4);
            }
            uint32_t* d1 = sA + node * KP128 + q * 4;
            uint32_t* dd2 = d1 + 64;
            d1[0] = f2tf(v1.x); d1[1] = f2tf(v1.y); d1[2] = f2tf(v1.z); d1[3] = f2tf(v1.w);
            dd2[0] = f2tf(v2.x); dd2[1] = f2tf(v2.y); dd2[2] = f2tf(v2.z); dd2[3] = f2tf(v2.w);
        }
        __syncthreads();

        // phase 1: gg = [x1|x2] @ Wc^T + bc
        {
            float4 acc[4] = {};
#pragma unroll 4
            for (int ks = 0; ks < 16; ks++) {
                int ko = ks * 8;
                uint32_t a0 = sA[(r0 + g) * KP128 + ko + tig];
                uint32_t a1 = sA[(r0 + g + 8) * KP128 + ko + tig];
                uint32_t a2 = sA[(r0 + g) * KP128 + ko + tig + 4];
                uint32_t a3 = sA[(r0 + g + 8) * KP128 + ko + tig + 4];
#pragma unroll
                for (int nt = 0; nt < 4; nt++) {
                    int o = cb + nt * 8 + g;
                    mma8(acc[nt], a0, a1, a2, a3,
                         sWc[o * KP128 + ko + tig], sWc[o * KP128 + ko + tig + 4]);
                }
            }
#pragma unroll
            for (int nt = 0; nt < 4; nt++) {
                int c = cb + nt * 8 + tig * 2;
                sG[(r0 + g) * KP64 + c]         = f2tf(acc[nt].x + sbc[c]);
                sG[(r0 + g) * KP64 + c + 1]     = f2tf(acc[nt].y + sbc[c + 1]);
                sG[(r0 + g + 8) * KP64 + c]     = f2tf(acc[nt].z + sbc[c]);
                sG[(r0 + g + 8) * KP64 + c + 1] = f2tf(acc[nt].w + sbc[c + 1]);
            }
        }
        __syncthreads();

        // phase 2: gi = gg @ Wih^T
        float4 d2[3][4];
#pragma unroll
        for (int gt = 0; gt < 3; gt++)
#pragma unroll
            for (int nt = 0; nt < 4; nt++)
                d2[gt][nt] = make_float4(0.f, 0.f, 0.f, 0.f);
        for (int ks = 0; ks < 8; ks++) {
            int ko = ks * 8;
            uint32_t a0 = sG[(r0 + g) * KP64 + ko + tig];
            uint32_t a1 = sG[(r0 + g + 8) * KP64 + ko + tig];
            uint32_t a2 = sG[(r0 + g) * KP64 + ko + tig + 4];
            uint32_t a3 = sG[(r0 + g + 8) * KP64 + ko + tig + 4];
#pragma unroll
            for (int gt = 0; gt < 3; gt++)
#pragma unroll
                for (int nt = 0; nt < 4; nt++) {
                    int o = gt * 64 + cb + nt * 8 + g;
                    mma8(d2[gt][nt], a0, a1, a2, a3,
                         sWih[o * KP64 + ko + tig], sWih[o * KP64 + ko + tig + 4]);
                }
        }

        // phase 3: GRU elementwise
        float hn[4][4];
#pragma unroll
        for (int nt = 0; nt < 4; nt++) {
            int c = cb + nt * 8 + tig * 2;
#pragma unroll
            for (int half = 0; half < 2; half++) {
                int node = base + r0 + g + half * 8;
                float vr0 = half ? d2[0][nt].z : d2[0][nt].x;
                float vr1 = half ? d2[0][nt].w : d2[0][nt].y;
                float vz0 = half ? d2[1][nt].z : d2[1][nt].x;
                float vz1 = half ? d2[1][nt].w : d2[1][nt].y;
                float vn0 = half ? d2[2][nt].z : d2[2][nt].x;
                float vn1 = half ? d2[2][nt].w : d2[2][nt].y;
                float o0 = 0.f, o1 = 0.f;
                if (node < NN) {
                    float2 gr = __half22float2(*(const __half2*)(g_ghhh + node * 192 + c));
                    float2 gz = __half22float2(*(const __half2*)(g_ghhh + node * 192 + 64 + c));
                    float2 gn = __half22float2(*(const __half2*)(g_ghhh + node * 192 + 128 + c));
                    float2 h  = *(const float2*)(g_h0 + node * HH + c);
                    float r = sigf(vr0 + sbih[c] + gr.x);
                    float z = sigf(vz0 + sbih[64 + c] + gz.x);
                    float n = tanhf(vn0 + sbih[128 + c] + r * gn.x);
                    o0 = (1.f - z) * n + z * h.x;
                    r = sigf(vr1 + sbih[c + 1] + gr.y);
                    z = sigf(vz1 + sbih[64 + c + 1] + gz.y);
                    n = tanhf(vn1 + sbih[128 + c + 1] + r * gn.y);
                    o1 = (1.f - z) * n + z * h.y;
                }
                hn[nt][half * 2] = o0;
                hn[nt][half * 2 + 1] = o1;
            }
        }
        __syncthreads();
#pragma unroll
        for (int nt = 0; nt < 4; nt++) {
            int c = cb + nt * 8 + tig * 2;
            sG[(r0 + g) * KP64 + c]         = f2tf(hn[nt][0]);
            sG[(r0 + g) * KP64 + c + 1]     = f2tf(hn[nt][1]);
            sG[(r0 + g + 8) * KP64 + c]     = f2tf(hn[nt][2]);
            sG[(r0 + g + 8) * KP64 + c + 1] = f2tf(hn[nt][3]);
        }
        __syncthreads();

        // phase 4: output GEMM
        if (!FINAL) {
            float4 acc[4] = {};
            for (int ks = 0; ks < 8; ks++) {
                int ko = ks * 8;
                uint32_t a0 = sG[(r0 + g) * KP64 + ko + tig];
                uint32_t a1 = sG[(r0 + g + 8) * KP64 + ko + tig];
                uint32_t a2 = sG[(r0 + g) * KP64 + ko + tig + 4];
                uint32_t a3 = sG[(r0 + g + 8) * KP64 + ko + tig + 4];
#pragma unroll
                for (int nt = 0; nt < 4; nt++) {
                    int o = cb + nt * 8 + g;
                    mma8(acc[nt], a0, a1, a2, a3,
                         sWl[o * KP64 + ko + tig], sWl[o * KP64 + ko + tig + 4]);
                }
            }
#pragma unroll
            for (int nt = 0; nt < 4; nt++) {
                int c = cb + nt * 8 + tig * 2;
                int n1 = base + r0 + g, n2 = n1 + 8;
                if (n1 < NN)
                    *(__half2*)(g_xmidh + n1 * HH + c) =
                        __floats2half2_rn(acc[nt].x + sbl[c], acc[nt].y + sbl[c + 1]);
                if (n2 < NN)
                    *(__half2*)(g_xmidh + n2 * HH + c) =
                        __floats2half2_rn(acc[nt].z + sbl[c], acc[nt].w + sbl[c + 1]);
            }
        } else {
            float4 acc = make_float4(0.f, 0.f, 0.f, 0.f);
            int c0f = (w >> 3) * 8;
            for (int ks = 0; ks < 8; ks++) {
                int ko = ks * 8;
                uint32_t a0 = sG[(r0 + g) * KP64 + ko + tig];
                uint32_t a1 = sG[(r0 + g + 8) * KP64 + ko + tig];
                uint32_t a2 = sG[(r0 + g) * KP64 + ko + tig + 4];
                uint32_t a3 = sG[(r0 + g + 8) * KP64 + ko + tig + 4];
                int o = c0f + g;
                mma8(acc, a0, a1, a2, a3,
                     sWl[o * KP64 + ko + tig], sWl[o * KP64 + ko + tig + 4]);
            }
            int c = c0f + tig * 2;
            sLY[(r0 + g) * 17 + c]         = acc.x + sbl[c];
            sLY[(r0 + g) * 17 + c + 1]     = acc.y + sbl[c + 1];
            sLY[(r0 + g + 8) * 17 + c]     = acc.z + sbl[c];
            sLY[(r0 + g + 8) * 17 + c + 1] = acc.w + sbl[c + 1];
            __syncthreads();
            if (t < 128) {
                int node = base + t;
                if (node < NN) {
                    float m = -1e30f;
#pragma unroll
                    for (int cc = 0; cc < 16; cc++) m = fmaxf(m, sLY[t * 17 + cc]);
                    float s = 0.f;
#pragma unroll
                    for (int cc = 0; cc < 16; cc++) s += expf(sLY[t * 17 + cc] - m);
                    float l = m + logf(s);
#pragma unroll
                    for (int cc = 0; cc < 16; cc++)
                        dout[node * CC + cc] = sLY[t * 17 + cc] - l;
                }
            }
        }
        __syncthreads();
    }
}

// ---------------- launch -----------------------------------------------------
extern "C" void kernel_launch(void* const* d_in, const int* in_sizes, int n_in,
                              void* d_out, int out_size) {
    const float* x       = (const float*)d_in[0];
    const int*   ei      = (const int*)  d_in[1];
    const float* ew      = (const float*)d_in[2];
    const int*   eir     = (const int*)  d_in[3];
    const float* ewr     = (const float*)d_in[4];
    const float* W_first = (const float*)d_in[5];
    const float* b_first = (const float*)d_in[6];
    const float* W_con1  = (const float*)d_in[7];
    const float* b_con1  = (const float*)d_in[8];
    const float* W_con2  = (const float*)d_in[9];
    const float* b_con2  = (const float*)d_in[10];
    const float* W_lin1  = (const float*)d_in[11];
    const float* b_lin1  = (const float*)d_in[12];
    const float* W_out   = (const float*)d_in[13];
    const float* b_out   = (const float*)d_in[14];
    const float* W_ih    = (const float*)d_in[15];
    const float* W_hh    = (const float*)d_in[16];
    const float* b_ih    = (const float*)d_in[17];
    const float* b_hh    = (const float*)d_in[18];
    float* out = (float*)d_out;

    const int SM_FG = FG_WORDS * 4;
    const int SM_CG = CG_WORDS * 4;

    cudaFuncSetAttribute(k_fg, cudaFuncAttributeMaxDynamicSharedMemorySize, SM_FG);
    cudaFuncSetAttribute(k_congru<false>,
                         cudaFuncAttributeMaxDynamicSharedMemorySize, SM_CG);
    cudaFuncSetAttribute(k_congru<true>,
                         cudaFuncAttributeMaxDynamicSharedMemorySize, SM_CG);

    const int PERS = 148;                     // persistent: 1 CTA per SM
    const int PROP_BLOCKS = (2 * EE) / 32;

    k_zero<<<1024, 256>>>();
    k_fg<<<PERS, 512, SM_FG>>>(x, W_first, b_first, W_hh, b_hh);
    k_prop<<<PROP_BLOCKS, 256>>>(0, ei, ew, eir, ewr);
    k_congru<false><<<PERS, 512, SM_CG>>>(W_con1, b_con1, W_ih, b_ih,
                                          W_lin1, b_lin1, nullptr);
    k_zero<<<1024, 256>>>();
    k_prop<<<PROP_BLOCKS, 256>>>(1, ei, ew, eir, ewr);
    k_congru<true><<<PERS, 512, SM_CG>>>(W_con2, b_con2, W_ih, b_ih,
                                         W_out, b_out, out);
}

// round 6
// speedup vs baseline: 7.6823x; 1.0372x over previous
#include <cuda_runtime.h>
#include <cuda_fp16.h>
#include <math.h>
#include <stdint.h>

#define NN 100000
#define FF 128
#define HH 64
#define CC 16
#define EE 1000000
#define KP128 132
#define KP64 68
#define NB 782   // ceil(NN/128)

// ---------------- scratch ----------------------------------------------------
__device__ __align__(16) float  g_h0[NN * HH];
__device__ __align__(16) __half g_h0h[NN * HH];
__device__ __align__(16) __half g_xmidh[NN * HH];
__device__ __align__(16) __half g_ghhh[NN * 192];
__device__ __align__(16) float  g_x1[NN * HH];
__device__ __align__(16) float  g_x2[NN * HH];

// ---------------- tf32 mma helpers ------------------------------------------
__device__ __forceinline__ uint32_t f2tf(float f) {
    uint32_t u;
    asm("cvt.rna.tf32.f32 %0, %1;" : "=r"(u) : "f"(f));
    return u;
}
__device__ __forceinline__ void mma8(float4& d, uint32_t a0, uint32_t a1,
                                     uint32_t a2, uint32_t a3,
                                     uint32_t b0, uint32_t b1) {
    asm volatile(
        "mma.sync.aligned.m16n8k8.row.col.f32.tf32.tf32.f32 "
        "{%0,%1,%2,%3},{%4,%5,%6,%7},{%8,%9},{%0,%1,%2,%3};"
        : "+f"(d.x), "+f"(d.y), "+f"(d.z), "+f"(d.w)
        : "r"(a0), "r"(a1), "r"(a2), "r"(a3), "r"(b0), "r"(b1));
}
__device__ __forceinline__ float sigf(float x) {
    return 1.f / (1.f + __expf(-x));
}

// ---------------- zero the two scatter buffers -------------------------------
__global__ void k_zero() {
    const int tot = NN * HH / 4;
    float4 z = make_float4(0.f, 0.f, 0.f, 0.f);
    for (int i = blockIdx.x * blockDim.x + threadIdx.x; i < tot;
         i += gridDim.x * blockDim.x) {
        reinterpret_cast<float4*>(g_x1)[i] = z;
        reinterpret_cast<float4*>(g_x2)[i] = z;
    }
}

// ---------------- persistent k_fg: h0 = x@Wf^T+bf ; ghh = h0@Whh^T+bhh -------
#define FG_A    0                          // 128x132
#define FG_WF   (FG_A + 128 * KP128)       // 64x132
#define FG_WHH  (FG_WF + 64 * KP128)       // 192x68
#define FG_G    (FG_WHH + 192 * KP64)      // 128x68
#define FG_WORDS (FG_G + 128 * KP64)

__global__ __launch_bounds__(1024, 1) void k_fg(const float* __restrict__ x,
                                                const float* __restrict__ Wf,
                                                const float* __restrict__ bf,
                                                const float* __restrict__ Whh,
                                                const float* __restrict__ bhh) {
    extern __shared__ uint32_t sm[];
    uint32_t* sA   = sm + FG_A;
    uint32_t* sWf  = sm + FG_WF;
    uint32_t* sWhh = sm + FG_WHH;
    uint32_t* sG   = sm + FG_G;
    __shared__ float sbf[64];
    __shared__ float sbhh[192];
    int t = threadIdx.x;

    // stage weights ONCE
    for (int i = t; i < 64 * 32; i += 1024) {
        int o = i >> 5, q = i & 31;
        float4 v = *(const float4*)(Wf + o * FF + q * 4);
        uint32_t* d = sWf + o * KP128 + q * 4;
        d[0] = f2tf(v.x); d[1] = f2tf(v.y); d[2] = f2tf(v.z); d[3] = f2tf(v.w);
    }
    for (int i = t; i < 192 * 16; i += 1024) {
        int o = i >> 4, q = i & 15;
        float4 v = *(const float4*)(Whh + o * HH + q * 4);
        uint32_t* d = sWhh + o * KP64 + q * 4;
        d[0] = f2tf(v.x); d[1] = f2tf(v.y); d[2] = f2tf(v.z); d[3] = f2tf(v.w);
    }
    if (t < 64) sbf[t] = bf[t];
    if (t >= 256 && t < 448) sbhh[t - 256] = bhh[t - 256];
    __syncthreads();

    int w = t >> 5, lane = t & 31, g = lane >> 2, tig = lane & 3;
    int r0 = (w & 7) * 16, cw = w >> 3;   // 8 row groups x 4 col groups

    for (int tile = blockIdx.x; tile < NB; tile += gridDim.x) {
        int base = tile * 128;
        for (int i = t; i < 128 * 32; i += 1024) {
            int node = i >> 5, q = i & 31;
            float4 v = make_float4(0.f, 0.f, 0.f, 0.f);
            if (base + node < NN)
                v = *(const float4*)(x + (base + node) * FF + q * 4);
            uint32_t* d = sA + node * KP128 + q * 4;
            d[0] = f2tf(v.x); d[1] = f2tf(v.y); d[2] = f2tf(v.z); d[3] = f2tf(v.w);
        }
        __syncthreads();

        // GEMM1: h0 = x @ Wf^T  (64 cols -> 2 n-tiles per warp)
        {
            int cb = cw * 16;
            float4 acc[2] = {};
#pragma unroll 4
            for (int ks = 0; ks < 16; ks++) {
                int ko = ks * 8;
                uint32_t a0 = sA[(r0 + g) * KP128 + ko + tig];
                uint32_t a1 = sA[(r0 + g + 8) * KP128 + ko + tig];
                uint32_t a2 = sA[(r0 + g) * KP128 + ko + tig + 4];
                uint32_t a3 = sA[(r0 + g + 8) * KP128 + ko + tig + 4];
#pragma unroll
                for (int nt = 0; nt < 2; nt++) {
                    int o = cb + nt * 8 + g;
                    mma8(acc[nt], a0, a1, a2, a3,
                         sWf[o * KP128 + ko + tig], sWf[o * KP128 + ko + tig + 4]);
                }
            }
#pragma unroll
            for (int nt = 0; nt < 2; nt++) {
                int c = cb + nt * 8 + tig * 2;
                int n1 = base + r0 + g, n2 = n1 + 8;
                float v0 = acc[nt].x + sbf[c], v1 = acc[nt].y + sbf[c + 1];
                float v2 = acc[nt].z + sbf[c], v3 = acc[nt].w + sbf[c + 1];
                if (n1 < NN) {
                    *(float2*)(g_h0 + n1 * HH + c) = make_float2(v0, v1);
                    *(__half2*)(g_h0h + n1 * HH + c) = __floats2half2_rn(v0, v1);
                }
                if (n2 < NN) {
                    *(float2*)(g_h0 + n2 * HH + c) = make_float2(v2, v3);
                    *(__half2*)(g_h0h + n2 * HH + c) = __floats2half2_rn(v2, v3);
                }
                sG[(r0 + g) * KP64 + c]         = f2tf(v0);
                sG[(r0 + g) * KP64 + c + 1]     = f2tf(v1);
                sG[(r0 + g + 8) * KP64 + c]     = f2tf(v2);
                sG[(r0 + g + 8) * KP64 + c + 1] = f2tf(v3);
            }
        }
        __syncthreads();

        // GEMM2: ghh = h0 @ Whh^T  (192 cols -> 6 n-tiles per warp)
        {
            int cb = cw * 48;
            float4 acc[6] = {};
            for (int ks = 0; ks < 8; ks++) {
                int ko = ks * 8;
                uint32_t a0 = sG[(r0 + g) * KP64 + ko + tig];
                uint32_t a1 = sG[(r0 + g + 8) * KP64 + ko + tig];
                uint32_t a2 = sG[(r0 + g) * KP64 + ko + tig + 4];
                uint32_t a3 = sG[(r0 + g + 8) * KP64 + ko + tig + 4];
#pragma unroll
                for (int nt = 0; nt < 6; nt++) {
                    int o = cb + nt * 8 + g;
                    mma8(acc[nt], a0, a1, a2, a3,
                         sWhh[o * KP64 + ko + tig], sWhh[o * KP64 + ko + tig + 4]);
                }
            }
#pragma unroll
            for (int nt = 0; nt < 6; nt++) {
                int c = cb + nt * 8 + tig * 2;
                int n1 = base + r0 + g, n2 = n1 + 8;
                if (n1 < NN)
                    *(__half2*)(g_ghhh + n1 * 192 + c) =
                        __floats2half2_rn(acc[nt].x + sbhh[c], acc[nt].y + sbhh[c + 1]);
                if (n2 < NN)
                    *(__half2*)(g_ghhh + n2 * 192 + c) =
                        __floats2half2_rn(acc[nt].z + sbhh[c], acc[nt].w + sbhh[c + 1]);
            }
        }
        __syncthreads();
    }
}

// ---------------- edge propagation: fp16 gather, fp32 RED, 2 edges/thread ----
__global__ __launch_bounds__(256) void k_prop(int use_mid,
                                              const int* __restrict__ ei1,
                                              const float* __restrict__ ew1,
                                              const int* __restrict__ ei2,
                                              const float* __restrict__ ew2) {
    const __half* xin = use_mid ? g_xmidh : g_h0h;
    int group = blockIdx.x * 16 + (threadIdx.x >> 4);
    int l16 = threadIdx.x & 15;
    int slot0 = group * 2;

    const int* ei;
    const float* ew;
    float* out;
    int e0;
    if (slot0 < EE) { e0 = slot0;      ei = ei1; ew = ew1; out = g_x1; }
    else            { e0 = slot0 - EE; ei = ei2; ew = ew2; out = g_x2; }

    int s0 = __ldg(ei + e0),      s1 = __ldg(ei + e0 + 1);
    int d0 = __ldg(ei + EE + e0), d1 = __ldg(ei + EE + e0 + 1);
    float w0 = __ldg(ew + e0),    w1 = __ldg(ew + e0 + 1);

    const __half2* p0 = (const __half2*)(xin + s0 * HH + l16 * 4);
    const __half2* p1 = (const __half2*)(xin + s1 * HH + l16 * 4);
    __half2 a0 = p0[0], a1 = p0[1];
    __half2 b0 = p1[0], b1 = p1[1];

    float2 f0 = __half22float2(a0), f1 = __half22float2(a1);
    float2 g0 = __half22float2(b0), g1 = __half22float2(b1);

    float* q0 = out + d0 * HH + l16 * 4;
    float* q1 = out + d1 * HH + l16 * 4;
    asm volatile("red.global.add.v4.f32 [%0], {%1, %2, %3, %4};"
                 :: "l"(q0), "f"(f0.x * w0), "f"(f0.y * w0),
                    "f"(f1.x * w0), "f"(f1.y * w0) : "memory");
    asm volatile("red.global.add.v4.f32 [%0], {%1, %2, %3, %4};"
                 :: "l"(q1), "f"(g0.x * w1), "f"(g0.y * w1),
                    "f"(g1.x * w1), "f"(g1.y * w1) : "memory");
}

// ---------------- persistent fused concat-linear + GRU + out ----------------
#define O_A    0
#define O_WC   (O_A + 128 * KP128)
#define O_WIH  (O_WC + 64 * KP128)
#define O_WL   (O_WIH + 192 * KP64)
#define O_G    (O_WL + 64 * KP64)
#define O_BC   (O_G + 128 * KP64)
#define O_BIH  (O_BC + 64)
#define O_BL   (O_BIH + 192)
#define O_LY   (O_BL + 64)
#define CG_WORDS (O_LY + 128 * 17)

template <bool FINAL>
__global__ __launch_bounds__(1024, 1) void k_congru(
    const float* __restrict__ Wc,  const float* __restrict__ bc,
    const float* __restrict__ Wih, const float* __restrict__ bih,
    const float* __restrict__ Wl,  const float* __restrict__ bl,
    float* __restrict__ dout) {
    extern __shared__ uint32_t sm[];
    uint32_t* sA   = sm + O_A;
    uint32_t* sWc  = sm + O_WC;
    uint32_t* sWih = sm + O_WIH;
    uint32_t* sWl  = sm + O_WL;
    uint32_t* sG   = sm + O_G;
    float* sbc  = (float*)(sm + O_BC);
    float* sbih = (float*)(sm + O_BIH);
    float* sbl  = (float*)(sm + O_BL);
    float* sLY  = (float*)(sm + O_LY);
    const int OC = FINAL ? CC : HH;

    int t = threadIdx.x;

    // stage weights ONCE
    for (int i = t; i < 64 * 32; i += 1024) {
        int o = i >> 5, q = i & 31;
        float4 v = *(const float4*)(Wc + o * FF + q * 4);
        uint32_t* d = sWc + o * KP128 + q * 4;
        d[0] = f2tf(v.x); d[1] = f2tf(v.y); d[2] = f2tf(v.z); d[3] = f2tf(v.w);
    }
    for (int i = t; i < 192 * 16; i += 1024) {
        int o = i >> 4, q = i & 15;
        float4 v = *(const float4*)(Wih + o * HH + q * 4);
        uint32_t* d = sWih + o * KP64 + q * 4;
        d[0] = f2tf(v.x); d[1] = f2tf(v.y); d[2] = f2tf(v.z); d[3] = f2tf(v.w);
    }
    for (int i = t; i < OC * 16; i += 1024) {
        int o = i >> 4, q = i & 15;
        float4 v = *(const float4*)(Wl + o * HH + q * 4);
        uint32_t* d = sWl + o * KP64 + q * 4;
        d[0] = f2tf(v.x); d[1] = f2tf(v.y); d[2] = f2tf(v.z); d[3] = f2tf(v.w);
    }
    if (t < 64)  sbc[t]  = bc[t];
    if (t < 192) sbih[t] = bih[t];
    if (t < OC)  sbl[t]  = bl[t];
    __syncthreads();

    int w = t >> 5, lane = t & 31, g = lane >> 2, tig = lane & 3;
    int r0 = (w & 7) * 16, cw = w >> 3, cb = cw * 16;

    for (int tile = blockIdx.x; tile < NB; tile += gridDim.x) {
        int base = tile * 128;
        for (int i = t; i < 128 * 16; i += 1024) {
            int node = i >> 4, q = i & 15;
            int n = base + node;
            float4 v1 = make_float4(0.f, 0.f, 0.f, 0.f), v2 = v1;
            if (n < NN) {
                v1 = *(const float4*)(g_x1 + n * HH + q * 4);
                v2 = *(const float4*)(g_x2 + n * HH + q * 4);
            }
            uint32_t* d1 = sA + node * KP128 + q * 4;
            uint32_t* dd2 = d1 + 64;
            d1[0] = f2tf(v1.x); d1[1] = f2tf(v1.y); d1[2] = f2tf(v1.z); d1[3] = f2tf(v1.w);
            dd2[0] = f2tf(v2.x); dd2[1] = f2tf(v2.y); dd2[2] = f2tf(v2.z); dd2[3] = f2tf(v2.w);
        }
        __syncthreads();

        // phase 1: gg = [x1|x2] @ Wc^T + bc  (2 n-tiles per warp)
        {
            float4 acc[2] = {};
#pragma unroll 4
            for (int ks = 0; ks < 16; ks++) {
                int ko = ks * 8;
                uint32_t a0 = sA[(r0 + g) * KP128 + ko + tig];
                uint32_t a1 = sA[(r0 + g + 8) * KP128 + ko + tig];
                uint32_t a2 = sA[(r0 + g) * KP128 + ko + tig + 4];
                uint32_t a3 = sA[(r0 + g + 8) * KP128 + ko + tig + 4];
#pragma unroll
                for (int nt = 0; nt < 2; nt++) {
                    int o = cb + nt * 8 + g;
                    mma8(acc[nt], a0, a1, a2, a3,
                         sWc[o * KP128 + ko + tig], sWc[o * KP128 + ko + tig + 4]);
                }
            }
#pragma unroll
            for (int nt = 0; nt < 2; nt++) {
                int c = cb + nt * 8 + tig * 2;
                sG[(r0 + g) * KP64 + c]         = f2tf(acc[nt].x + sbc[c]);
                sG[(r0 + g) * KP64 + c + 1]     = f2tf(acc[nt].y + sbc[c + 1]);
                sG[(r0 + g + 8) * KP64 + c]     = f2tf(acc[nt].z + sbc[c]);
                sG[(r0 + g + 8) * KP64 + c + 1] = f2tf(acc[nt].w + sbc[c + 1]);
            }
        }
        __syncthreads();

        // phase 2: gi = gg @ Wih^T  (3 gates x 2 n-tiles per warp)
        float4 d2[3][2];
#pragma unroll
        for (int gt = 0; gt < 3; gt++)
#pragma unroll
            for (int nt = 0; nt < 2; nt++)
                d2[gt][nt] = make_float4(0.f, 0.f, 0.f, 0.f);
        for (int ks = 0; ks < 8; ks++) {
            int ko = ks * 8;
            uint32_t a0 = sG[(r0 + g) * KP64 + ko + tig];
            uint32_t a1 = sG[(r0 + g + 8) * KP64 + ko + tig];
            uint32_t a2 = sG[(r0 + g) * KP64 + ko + tig + 4];
            uint32_t a3 = sG[(r0 + g + 8) * KP64 + ko + tig + 4];
#pragma unroll
            for (int gt = 0; gt < 3; gt++)
#pragma unroll
                for (int nt = 0; nt < 2; nt++) {
                    int o = gt * 64 + cb + nt * 8 + g;
                    mma8(d2[gt][nt], a0, a1, a2, a3,
                         sWih[o * KP64 + ko + tig], sWih[o * KP64 + ko + tig + 4]);
                }
        }

        // phase 3: GRU elementwise
        float hn[2][4];
#pragma unroll
        for (int nt = 0; nt < 2; nt++) {
            int c = cb + nt * 8 + tig * 2;
#pragma unroll
            for (int half = 0; half < 2; half++) {
                int node = base + r0 + g + half * 8;
                float vr0 = half ? d2[0][nt].z : d2[0][nt].x;
                float vr1 = half ? d2[0][nt].w : d2[0][nt].y;
                float vz0 = half ? d2[1][nt].z : d2[1][nt].x;
                float vz1 = half ? d2[1][nt].w : d2[1][nt].y;
                float vn0 = half ? d2[2][nt].z : d2[2][nt].x;
                float vn1 = half ? d2[2][nt].w : d2[2][nt].y;
                float o0 = 0.f, o1 = 0.f;
                if (node < NN) {
                    float2 gr = __half22float2(*(const __half2*)(g_ghhh + node * 192 + c));
                    float2 gz = __half22float2(*(const __half2*)(g_ghhh + node * 192 + 64 + c));
                    float2 gn = __half22float2(*(const __half2*)(g_ghhh + node * 192 + 128 + c));
                    float2 h  = *(const float2*)(g_h0 + node * HH + c);
                    float r = sigf(vr0 + sbih[c] + gr.x);
                    float z = sigf(vz0 + sbih[64 + c] + gz.x);
                    float n = tanhf(vn0 + sbih[128 + c] + r * gn.x);
                    o0 = (1.f - z) * n + z * h.x;
                    r = sigf(vr1 + sbih[c + 1] + gr.y);
                    z = sigf(vz1 + sbih[64 + c + 1] + gz.y);
                    n = tanhf(vn1 + sbih[128 + c + 1] + r * gn.y);
                    o1 = (1.f - z) * n + z * h.y;
                }
                hn[nt][half * 2] = o0;
                hn[nt][half * 2 + 1] = o1;
            }
        }
        __syncthreads();
#pragma unroll
        for (int nt = 0; nt < 2; nt++) {
            int c = cb + nt * 8 + tig * 2;
            sG[(r0 + g) * KP64 + c]         = f2tf(hn[nt][0]);
            sG[(r0 + g) * KP64 + c + 1]     = f2tf(hn[nt][1]);
            sG[(r0 + g + 8) * KP64 + c]     = f2tf(hn[nt][2]);
            sG[(r0 + g + 8) * KP64 + c + 1] = f2tf(hn[nt][3]);
        }
        __syncthreads();

        // phase 4: output GEMM
        if (!FINAL) {
            float4 acc[2] = {};
            for (int ks = 0; ks < 8; ks++) {
                int ko = ks * 8;
                uint32_t a0 = sG[(r0 + g) * KP64 + ko + tig];
                uint32_t a1 = sG[(r0 + g + 8) * KP64 + ko + tig];
                uint32_t a2 = sG[(r0 + g) * KP64 + ko + tig + 4];
                uint32_t a3 = sG[(r0 + g + 8) * KP64 + ko + tig + 4];
#pragma unroll
                for (int nt = 0; nt < 2; nt++) {
                    int o = cb + nt * 8 + g;
                    mma8(acc[nt], a0, a1, a2, a3,
                         sWl[o * KP64 + ko + tig], sWl[o * KP64 + ko + tig + 4]);
                }
            }
#pragma unroll
            for (int nt = 0; nt < 2; nt++) {
                int c = cb + nt * 8 + tig * 2;
                int n1 = base + r0 + g, n2 = n1 + 8;
                if (n1 < NN)
                    *(__half2*)(g_xmidh + n1 * HH + c) =
                        __floats2half2_rn(acc[nt].x + sbl[c], acc[nt].y + sbl[c + 1]);
                if (n2 < NN)
                    *(__half2*)(g_xmidh + n2 * HH + c) =
                        __floats2half2_rn(acc[nt].z + sbl[c], acc[nt].w + sbl[c + 1]);
            }
        } else {
            // 16 cols = 2 n-tiles; col groups 0,1 do the work
            if (cw < 2) {
                float4 acc = make_float4(0.f, 0.f, 0.f, 0.f);
                int c0f = cw * 8;
                for (int ks = 0; ks < 8; ks++) {
                    int ko = ks * 8;
                    uint32_t a0 = sG[(r0 + g) * KP64 + ko + tig];
                    uint32_t a1 = sG[(r0 + g + 8) * KP64 + ko + tig];
                    uint32_t a2 = sG[(r0 + g) * KP64 + ko + tig + 4];
                    uint32_t a3 = sG[(r0 + g + 8) * KP64 + ko + tig + 4];
                    int o = c0f + g;
                    mma8(acc, a0, a1, a2, a3,
                         sWl[o * KP64 + ko + tig], sWl[o * KP64 + ko + tig + 4]);
                }
                int c = c0f + tig * 2;
                sLY[(r0 + g) * 17 + c]         = acc.x + sbl[c];
                sLY[(r0 + g) * 17 + c + 1]     = acc.y + sbl[c + 1];
                sLY[(r0 + g + 8) * 17 + c]     = acc.z + sbl[c];
                sLY[(r0 + g + 8) * 17 + c + 1] = acc.w + sbl[c + 1];
            }
            __syncthreads();
            if (t < 128) {
                int node = base + t;
                if (node < NN) {
                    float m = -1e30f;
#pragma unroll
                    for (int cc = 0; cc < 16; cc++) m = fmaxf(m, sLY[t * 17 + cc]);
                    float s = 0.f;
#pragma unroll
                    for (int cc = 0; cc < 16; cc++) s += expf(sLY[t * 17 + cc] - m);
                    float l = m + logf(s);
#pragma unroll
                    for (int cc = 0; cc < 16; cc++)
                        dout[node * CC + cc] = sLY[t * 17 + cc] - l;
                }
            }
        }
        __syncthreads();
    }
}

// ---------------- launch -----------------------------------------------------
extern "C" void kernel_launch(void* const* d_in, const int* in_sizes, int n_in,
                              void* d_out, int out_size) {
    const float* x       = (const float*)d_in[0];
    const int*   ei      = (const int*)  d_in[1];
    const float* ew      = (const float*)d_in[2];
    const int*   eir     = (const int*)  d_in[3];
    const float* ewr     = (const float*)d_in[4];
    const float* W_first = (const float*)d_in[5];
    const float* b_first = (const float*)d_in[6];
    const float* W_con1  = (const float*)d_in[7];
    const float* b_con1  = (const float*)d_in[8];
    const float* W_con2  = (const float*)d_in[9];
    const float* b_con2  = (const float*)d_in[10];
    const float* W_lin1  = (const float*)d_in[11];
    const float* b_lin1  = (const float*)d_in[12];
    const float* W_out   = (const float*)d_in[13];
    const float* b_out   = (const float*)d_in[14];
    const float* W_ih    = (const float*)d_in[15];
    const float* W_hh    = (const float*)d_in[16];
    const float* b_ih    = (const float*)d_in[17];
    const float* b_hh    = (const float*)d_in[18];
    float* out = (float*)d_out;

    const int SM_FG = FG_WORDS * 4;
    const int SM_CG = CG_WORDS * 4;

    cudaFuncSetAttribute(k_fg, cudaFuncAttributeMaxDynamicSharedMemorySize, SM_FG);
    cudaFuncSetAttribute(k_congru<false>,
                         cudaFuncAttributeMaxDynamicSharedMemorySize, SM_CG);
    cudaFuncSetAttribute(k_congru<true>,
                         cudaFuncAttributeMaxDynamicSharedMemorySize, SM_CG);

    const int PERS = 148;                     // persistent: 1 CTA per SM
    const int PROP_BLOCKS = (2 * EE) / 32;

    k_zero<<<1024, 256>>>();
    k_fg<<<PERS, 1024, SM_FG>>>(x, W_first, b_first, W_hh, b_hh);
    k_prop<<<PROP_BLOCKS, 256>>>(0, ei, ew, eir, ewr);
    k_congru<false><<<PERS, 1024, SM_CG>>>(W_con1, b_con1, W_ih, b_ih,
                                           W_lin1, b_lin1, nullptr);
    k_zero<<<1024, 256>>>();
    k_prop<<<PROP_BLOCKS, 256>>>(1, ei, ew, eir, ewr);
    k_congru<true><<<PERS, 1024, SM_CG>>>(W_con2, b_con2, W_ih, b_ih,
                                          W_out, b_out, out);
}